// round 6
// baseline (speedup 1.0000x reference)
#include <cuda_runtime.h>
#include <cuda_bf16.h>
#include <cstdint>

// Problem constants
#define B_   64
#define N_   100
#define D_   2048
#define NR_  16
#define DK_  64
#define DV_  128
#define P_   (B_*N_)          // 6400
#define KQ_COLS (NR_*DK_)     // 1024
#define PAIRS (B_*N_*N_)      // 640000

// ---------------------------------------------------------------------------
// Scratch (device globals; allocation APIs are forbidden)
// ---------------------------------------------------------------------------
__device__ float g_K[P_ * KQ_COLS];          // 6400 x 1024
__device__ float g_Q[P_ * KQ_COLS];          // 6400 x 1024
__device__ float g_gwT[B_ * NR_ * N_ * N_];  // [b][h][i*100+j]

__device__ __align__(16) __nv_bfloat16 g_Ahi[P_ * D_];        // [m][k]
__device__ __align__(16) __nv_bfloat16 g_Alo[P_ * D_];
__device__ __align__(16) __nv_bfloat16 g_WKhi[D_ * KQ_COLS];  // [k][n]
__device__ __align__(16) __nv_bfloat16 g_WKlo[D_ * KQ_COLS];
__device__ __align__(16) __nv_bfloat16 g_WQhi[D_ * KQ_COLS];
__device__ __align__(16) __nv_bfloat16 g_WQlo[D_ * KQ_COLS];

// ---------------------------------------------------------------------------
// PTX helpers (baseline ISA only: cp.async / ldmatrix / mma.sync)
// ---------------------------------------------------------------------------
__device__ __forceinline__ uint32_t smem_u32(const void* p) {
    uint32_t a;
    asm("{ .reg .u64 t; cvta.to.shared.u64 t, %1; cvt.u32.u64 %0, t; }"
        : "=r"(a) : "l"(p));
    return a;
}
__device__ __forceinline__ void cp_async16(uint32_t dst, const void* src) {
    asm volatile("cp.async.cg.shared.global [%0], [%1], 16;" :: "r"(dst), "l"(src));
}
#define CP_COMMIT() asm volatile("cp.async.commit_group;" ::: "memory")
#define CP_WAIT(n)  asm volatile("cp.async.wait_group %0;" :: "n"(n) : "memory")

__device__ __forceinline__ void ldsm_x4(uint32_t addr, uint32_t* f) {
    asm volatile("ldmatrix.sync.aligned.m8n8.x4.shared.b16 {%0,%1,%2,%3}, [%4];"
                 : "=r"(f[0]), "=r"(f[1]), "=r"(f[2]), "=r"(f[3]) : "r"(addr));
}
__device__ __forceinline__ void ldsm_x4t(uint32_t addr, uint32_t* f) {
    asm volatile("ldmatrix.sync.aligned.m8n8.x4.trans.shared.b16 {%0,%1,%2,%3}, [%4];"
                 : "=r"(f[0]), "=r"(f[1]), "=r"(f[2]), "=r"(f[3]) : "r"(addr));
}
__device__ __forceinline__ void mma_bf16(float* d, const uint32_t* a, const uint32_t* b) {
    asm volatile("mma.sync.aligned.m16n8k16.row.col.f32.bf16.bf16.f32 "
                 "{%0,%1,%2,%3}, {%4,%5,%6,%7}, {%8,%9}, {%0,%1,%2,%3};"
                 : "+f"(d[0]), "+f"(d[1]), "+f"(d[2]), "+f"(d[3])
                 : "r"(a[0]), "r"(a[1]), "r"(a[2]), "r"(a[3]),
                   "r"(b[0]), "r"(b[1]));
}
__device__ __forceinline__ uint32_t pack_bf2(__nv_bfloat16 a, __nv_bfloat16 b) {
    __nv_bfloat162 t(a, b);
    return *(uint32_t*)&t;
}

// ---------------------------------------------------------------------------
// Kernel 1: gate.  2 pairs per thread (balance smem reuse vs occupancy).
// ---------------------------------------------------------------------------
__global__ __launch_bounds__(256) void gate_kernel(
    const float* __restrict__ G, const float* __restrict__ Wg,
    const float* __restrict__ bg, float* __restrict__ out)
{
    __shared__ float sW[64][16];
    __shared__ float sb[16];
    int tid = threadIdx.x;
    if (tid < 16) sb[tid] = bg[tid];
    for (int idx = tid; idx < 64 * 16; idx += 256)
        sW[idx >> 4][idx & 15] = Wg[idx];
    __syncthreads();

    int p0 = blockIdx.x * 512 + tid;   // pairs p0, p0+256

    float acc[2][16];
#pragma unroll
    for (int q = 0; q < 2; q++)
#pragma unroll
        for (int h = 0; h < 16; h++) acc[q][h] = sb[h];

    const float4* g4 = (const float4*)(G + (size_t)p0 * 64);

#pragma unroll 4
    for (int k4 = 0; k4 < 16; k4++) {
        float4 gv0 = g4[k4];
        float4 gv1 = g4[256 * 16 + k4];
#pragma unroll
        for (int e = 0; e < 4; e++) {
            int k = 4 * k4 + e;
            float4 w0 = *(const float4*)&sW[k][0];
            float4 w1 = *(const float4*)&sW[k][4];
            float4 w2 = *(const float4*)&sW[k][8];
            float4 w3 = *(const float4*)&sW[k][12];
            float wv[16] = {w0.x, w0.y, w0.z, w0.w, w1.x, w1.y, w1.z, w1.w,
                            w2.x, w2.y, w2.z, w2.w, w3.x, w3.y, w3.z, w3.w};
            float ge0 = (e == 0) ? gv0.x : (e == 1) ? gv0.y : (e == 2) ? gv0.z : gv0.w;
            float ge1 = (e == 0) ? gv1.x : (e == 1) ? gv1.y : (e == 2) ? gv1.z : gv1.w;
#pragma unroll
            for (int h = 0; h < 16; h++) {
                acc[0][h] += ge0 * wv[h];
                acc[1][h] += ge1 * wv[h];
            }
        }
    }

#pragma unroll
    for (int q = 0; q < 2; q++) {
        int p  = p0 + q * 256;
        int b  = p / (N_ * N_);
        int lp = p - b * (N_ * N_);
        float* ob = out + (size_t)b * (NR_ * N_ * N_) + lp;
#pragma unroll
        for (int h = 0; h < 16; h++)
            ob[(size_t)h * (N_ * N_)] = fmaxf(acc[q][h], 1e-6f);
    }
}

// ---------------------------------------------------------------------------
// Kernel 2: fp32 -> bf16 hi/lo (elementwise; used for A, W_K, W_Q)
// ---------------------------------------------------------------------------
__global__ __launch_bounds__(256) void conv_kernel(const float* __restrict__ X,
                                                   __nv_bfloat16* __restrict__ hi,
                                                   __nv_bfloat16* __restrict__ lo)
{
    int i = (blockIdx.x * 256 + threadIdx.x) * 4;
    float4 v = *(const float4*)(X + i);
    float xs[4] = {v.x, v.y, v.z, v.w};
    __nv_bfloat16 h[4], l[4];
#pragma unroll
    for (int e = 0; e < 4; e++) {
        h[e] = __float2bfloat16(xs[e]);
        l[e] = __float2bfloat16(xs[e] - __bfloat162float(h[e]));
    }
    *(__nv_bfloat162*)(hi + i)     = __nv_bfloat162(h[0], h[1]);
    *(__nv_bfloat162*)(hi + i + 2) = __nv_bfloat162(h[2], h[3]);
    *(__nv_bfloat162*)(lo + i)     = __nv_bfloat162(l[0], l[1]);
    *(__nv_bfloat162*)(lo + i + 2) = __nv_bfloat162(l[2], l[3]);
}

// ---------------------------------------------------------------------------
// Kernel 3: bf16 3-pass GEMM via mma.sync (unchanged from R5 win).
// ---------------------------------------------------------------------------
#define KC 64
#define NCHUNKS (D_ / KC)        // 32
#define STAGEBYTES 65536
#define GEMM_SMEM (3 * STAGEBYTES)

__global__ __launch_bounds__(256, 1) void gemm_mma(
    const __nv_bfloat16* __restrict__ Ah, const __nv_bfloat16* __restrict__ Al,
    const __nv_bfloat16* __restrict__ WKh, const __nv_bfloat16* __restrict__ WKl,
    const __nv_bfloat16* __restrict__ WQh, const __nv_bfloat16* __restrict__ WQl,
    const float* __restrict__ bK, const float* __restrict__ bQ,
    float* __restrict__ gK, float* __restrict__ gQ)
{
    extern __shared__ char smem[];
    uint32_t sbase = smem_u32(smem);
    int tid = threadIdx.x;
    int wid = tid >> 5, lane = tid & 31;
    int wm = wid >> 2, wn = wid & 3;   // 2 x 4 warp grid

    const __nv_bfloat16 *Wh, *Wl;
    const float* bias;
    float* C;
    if (blockIdx.z == 0) { Wh = WKh; Wl = WKl; bias = bK; C = gK; }
    else                 { Wh = WQh; Wl = WQl; bias = bQ; C = gQ; }

    int m0 = blockIdx.y * 128;
    int n0 = blockIdx.x * 128;

    float acc[4][4][4];
#pragma unroll
    for (int mi = 0; mi < 4; mi++)
#pragma unroll
        for (int nj = 0; nj < 4; nj++)
#pragma unroll
            for (int e = 0; e < 4; e++) acc[mi][nj][e] = 0.f;

    auto load_chunk = [&](int c, int s) {
        int k0 = c * KC;
        uint32_t base = sbase + s * STAGEBYTES;
#pragma unroll
        for (int t = 0; t < 2; t++) {
            const __nv_bfloat16* src = t ? Al : Ah;
#pragma unroll
            for (int l2 = 0; l2 < 4; l2++) {
                int id = tid + l2 * 256;
                int r = id >> 3, cc = id & 7;
                cp_async16(base + t * 16384 + r * 128 + ((cc ^ (r & 7)) << 4),
                           src + (size_t)(m0 + r) * 2048 + k0 + cc * 8);
            }
        }
#pragma unroll
        for (int t = 0; t < 2; t++) {
            const __nv_bfloat16* src = t ? Wl : Wh;
#pragma unroll
            for (int l2 = 0; l2 < 4; l2++) {
                int id = tid + l2 * 256;
                int k = id >> 4, cc = id & 15;
                cp_async16(base + 32768 + t * 16384 + k * 256 + ((cc ^ (k & 7)) << 4),
                           src + (size_t)(k0 + k) * 1024 + n0 + cc * 8);
            }
        }
        CP_COMMIT();
    };

    load_chunk(0, 0);
    load_chunk(1, 1);
    load_chunk(2, 2);

    int ar  = lane & 15;
    int acs = lane >> 4;
    int wg8 = lane >> 3;
    int wk8 = lane & 7;
    int wks = (wg8 & 1) * 8;
    int wns = wg8 >> 1;

    int s = 0;
    for (int c = 0; c < NCHUNKS; c++) {
        CP_WAIT(2);
        __syncthreads();
        uint32_t base = sbase + s * STAGEBYTES;

#pragma unroll
        for (int ki = 0; ki < 4; ki++) {
            uint32_t afh[4][4], afl[4][4];
#pragma unroll
            for (int mi = 0; mi < 4; mi++) {
                int r = wm * 64 + mi * 16 + ar;
                int cc = 2 * ki + acs;
                uint32_t off = (uint32_t)(r * 128 + ((cc ^ (r & 7)) << 4));
                ldsm_x4(base + off, afh[mi]);
                ldsm_x4(base + 16384 + off, afl[mi]);
            }
            uint32_t bfh[4][2], bfl[4][2];
#pragma unroll
            for (int nh = 0; nh < 2; nh++) {
                int k  = ki * 16 + wks + wk8;
                int cc = wn * 4 + 2 * nh + wns;
                uint32_t off = (uint32_t)(k * 256 + ((cc ^ (k & 7)) << 4));
                uint32_t q[4];
                ldsm_x4t(base + 32768 + off, q);
                bfh[2 * nh][0] = q[0]; bfh[2 * nh][1] = q[1];
                bfh[2 * nh + 1][0] = q[2]; bfh[2 * nh + 1][1] = q[3];
                ldsm_x4t(base + 49152 + off, q);
                bfl[2 * nh][0] = q[0]; bfl[2 * nh][1] = q[1];
                bfl[2 * nh + 1][0] = q[2]; bfl[2 * nh + 1][1] = q[3];
            }
#pragma unroll
            for (int mi = 0; mi < 4; mi++)
#pragma unroll
                for (int nj = 0; nj < 4; nj++) {
                    mma_bf16(acc[mi][nj], afh[mi], bfh[nj]);
                    mma_bf16(acc[mi][nj], afh[mi], bfl[nj]);
                    mma_bf16(acc[mi][nj], afl[mi], bfh[nj]);
                }
        }
        __syncthreads();
        if (c + 3 < NCHUNKS) load_chunk(c + 3, s); else CP_COMMIT();
        s = (s == 2) ? 0 : s + 1;
    }

    int g = lane >> 2, t4 = lane & 3;
    float bcol[4][2];
#pragma unroll
    for (int nj = 0; nj < 4; nj++) {
        int col = n0 + wn * 32 + nj * 8 + t4 * 2;
        bcol[nj][0] = __ldg(bias + col);
        bcol[nj][1] = __ldg(bias + col + 1);
    }
#pragma unroll
    for (int mi = 0; mi < 4; mi++) {
#pragma unroll
        for (int half = 0; half < 2; half++) {
            int m = m0 + wm * 64 + mi * 16 + g + half * 8;
            float* crow = C + (size_t)m * 1024 + n0 + wn * 32;
#pragma unroll
            for (int nj = 0; nj < 4; nj++) {
                int col = nj * 8 + t4 * 2;
                float2 v;
                v.x = acc[mi][nj][half * 2 + 0] + bcol[nj][0];
                v.y = acc[mi][nj][half * 2 + 1] + bcol[nj][1];
                *(float2*)(crow + col) = v;
            }
        }
    }
}

// ---------------------------------------------------------------------------
// Kernel 4: tensor-core attention, one block per (b,h).
//   S = K Q^T (bf16 3-pass mma), e = gw*exp(S/8), fin split hi/lo,
//   R = fin^T V (bf16 3-pass mma), out = R/colsum * ws + bs.
// smem (byte offsets):
//   Khi 0 (112x128B), Klo 14336, Qhi 28672, Qlo 43008,
//   finHi 57344 (112x256B), finLo 86016, Vhi 114688, Vlo 143360,
//   csum 172032 (112 f32).  Total 172480.
// Swizzle (128B rows): off = r*128 + ((cc ^ (r&7))<<4), cc = 16B chunk 0..7.
// Swizzle (256B rows): off = r*256 + ((cc ^ (r&7))<<4), cc = 16B chunk 0..15.
// ---------------------------------------------------------------------------
#define AT_KHI   0
#define AT_KLO   14336
#define AT_QHI   28672
#define AT_QLO   43008
#define AT_FHI   57344
#define AT_FLO   86016
#define AT_VHI   114688
#define AT_VLO   143360
#define AT_CSUM  172032
#define ATTN_SMEM 172480

__global__ __launch_bounds__(256, 1) void attn_kernel(
    const float* __restrict__ Kmat, const float* __restrict__ Qmat,
    const float* __restrict__ gw,
    const __nv_bfloat16* __restrict__ Vhi_g, const __nv_bfloat16* __restrict__ Vlo_g,
    const float* __restrict__ wsp, const float* __restrict__ bsp,
    float* __restrict__ out)
{
    extern __shared__ char smem[];
    uint32_t sbase = smem_u32(smem);
    float* csum = (float*)(smem + AT_CSUM);

    int h = blockIdx.x;
    int b = blockIdx.y;
    int tid = threadIdx.x;
    int wid = tid >> 5, lane = tid & 31;

    // --- Phase 0a: prefetch V (bf16 hi/lo from g_Ahi/g_Alo) via cp.async ---
    for (int idx = tid; idx < 1600; idx += 256) {
        int r = idx >> 4, cc = idx & 15;
        uint32_t off = (uint32_t)(r * 256 + ((cc ^ (r & 7)) << 4));
        const __nv_bfloat16* s1 = Vhi_g + (size_t)(b * 100 + r) * 2048 + h * 128 + cc * 8;
        const __nv_bfloat16* s2 = Vlo_g + (size_t)(b * 100 + r) * 2048 + h * 128 + cc * 8;
        cp_async16(sbase + AT_VHI + off, s1);
        cp_async16(sbase + AT_VLO + off, s2);
    }
    CP_COMMIT();

    // --- Phase 0b: zero pad rows (V,fin rows 100..111), csum ---
    uint4 z4 = {0u, 0u, 0u, 0u};
    for (int idx = tid; idx < 192; idx += 256) {
        int r = 100 + (idx >> 4), cc = idx & 15;
        uint32_t off = (uint32_t)(r * 256 + ((cc ^ (r & 7)) << 4));
        *(uint4*)(smem + AT_VHI + off) = z4;
        *(uint4*)(smem + AT_VLO + off) = z4;
        *(uint4*)(smem + AT_FHI + off) = z4;
        *(uint4*)(smem + AT_FLO + off) = z4;
    }
    if (tid < 112) csum[tid] = 0.f;

    // --- Phase 0c: load K,Q fp32 -> bf16 hi/lo smem (rows 0..99) ---
    for (int idx = tid; idx < 800; idx += 256) {
        int r = idx >> 3, cc = idx & 7;
        uint32_t off = (uint32_t)(r * 128 + ((cc ^ (r & 7)) << 4));
        const float* ks = Kmat + (size_t)(b * 100 + r) * 1024 + h * 64 + cc * 8;
        const float* qs = Qmat + (size_t)(b * 100 + r) * 1024 + h * 64 + cc * 8;
#pragma unroll
        for (int m = 0; m < 2; m++) {
            const float* src = m ? qs : ks;
            uint32_t dh = sbase + (m ? AT_QHI : AT_KHI) + off;
            uint32_t dl = sbase + (m ? AT_QLO : AT_KLO) + off;
            float4 v0 = *(const float4*)src;
            float4 v1 = *(const float4*)(src + 4);
            float xs[8] = {v0.x, v0.y, v0.z, v0.w, v1.x, v1.y, v1.z, v1.w};
            __nv_bfloat16 hh[8], ll[8];
#pragma unroll
            for (int e = 0; e < 8; e++) {
                hh[e] = __float2bfloat16(xs[e]);
                ll[e] = __float2bfloat16(xs[e] - __bfloat162float(hh[e]));
            }
            uint4 uh, ul;
            uh.x = pack_bf2(hh[0], hh[1]); uh.y = pack_bf2(hh[2], hh[3]);
            uh.z = pack_bf2(hh[4], hh[5]); uh.w = pack_bf2(hh[6], hh[7]);
            ul.x = pack_bf2(ll[0], ll[1]); ul.y = pack_bf2(ll[2], ll[3]);
            ul.z = pack_bf2(ll[4], ll[5]); ul.w = pack_bf2(ll[6], ll[7]);
            asm volatile("st.shared.v4.b32 [%0], {%1,%2,%3,%4};" ::
                "r"(dh), "r"(uh.x), "r"(uh.y), "r"(uh.z), "r"(uh.w) : "memory");
            asm volatile("st.shared.v4.b32 [%0], {%1,%2,%3,%4};" ::
                "r"(dl), "r"(ul.x), "r"(ul.y), "r"(ul.z), "r"(ul.w) : "memory");
        }
    }
    __syncthreads();

    const float* gwb = gw + ((size_t)(b * 16 + h)) * 10000;

    // --- Phase 1+2: S = K Q^T (warps 0..6, m-tile = wid), then e-phase ---
    if (wid < 7) {
        float acc[14][4];
#pragma unroll
        for (int nt = 0; nt < 14; nt++)
#pragma unroll
            for (int e = 0; e < 4; e++) acc[nt][e] = 0.f;

        // preload A (K) fragments for all 4 k-steps
        uint32_t afh[4][4], afl[4][4];
#pragma unroll
        for (int ks = 0; ks < 4; ks++) {
            int r = 16 * wid + (lane & 15);
            int cc = 2 * ks + (lane >> 4);
            uint32_t off = (uint32_t)(r * 128 + ((cc ^ (r & 7)) << 4));
            ldsm_x4(sbase + AT_KHI + off, afh[ks]);
            ldsm_x4(sbase + AT_KLO + off, afl[ks]);
        }
        int g = lane >> 3;
#pragma unroll
        for (int nt2 = 0; nt2 < 7; nt2++) {
#pragma unroll
            for (int ks = 0; ks < 4; ks++) {
                int jrow = nt2 * 16 + ((g & 2) ? 8 : 0) + (lane & 7);
                int cc = 2 * ks + (g & 1);
                uint32_t off = (uint32_t)(jrow * 128 + ((cc ^ (jrow & 7)) << 4));
                uint32_t qh[4], ql[4];
                ldsm_x4(sbase + AT_QHI + off, qh);
                ldsm_x4(sbase + AT_QLO + off, ql);
                uint32_t bh0[2] = {qh[0], qh[1]}, bh1[2] = {qh[2], qh[3]};
                uint32_t bl0[2] = {ql[0], ql[1]}, bl1[2] = {ql[2], ql[3]};
                mma_bf16(acc[2 * nt2],     afh[ks], bh0);
                mma_bf16(acc[2 * nt2],     afh[ks], bl0);
                mma_bf16(acc[2 * nt2],     afl[ks], bh0);
                mma_bf16(acc[2 * nt2 + 1], afh[ks], bh1);
                mma_bf16(acc[2 * nt2 + 1], afh[ks], bl1);
                mma_bf16(acc[2 * nt2 + 1], afl[ks], bh1);
            }
        }

        // e-phase: e = gw * exp(S/8); split hi/lo to fin; atomic column sums
        int row1 = 16 * wid + (lane >> 2);
        int row2 = row1 + 8;
        int jj   = (lane & 3) * 2;
#pragma unroll
        for (int nt = 0; nt < 14; nt++) {
            int j = nt * 8 + jj;
            float e0 = 0.f, e1 = 0.f, e2 = 0.f, e3 = 0.f;
            if (j < 100) {
                if (row1 < 100) {
                    float2 gv = *(const float2*)(gwb + row1 * 100 + j);
                    e0 = gv.x * __expf(acc[nt][0] * 0.125f);
                    e1 = gv.y * __expf(acc[nt][1] * 0.125f);
                }
                if (row2 < 100) {
                    float2 gv = *(const float2*)(gwb + row2 * 100 + j);
                    e2 = gv.x * __expf(acc[nt][2] * 0.125f);
                    e3 = gv.y * __expf(acc[nt][3] * 0.125f);
                }
                atomicAdd(&csum[j],     e0 + e2);
                atomicAdd(&csum[j + 1], e1 + e3);
            }
            // split + store (unconditional; zeros for padded/garbage regions)
            __nv_bfloat16 h0 = __float2bfloat16(e0);
            __nv_bfloat16 h1 = __float2bfloat16(e1);
            __nv_bfloat16 h2 = __float2bfloat16(e2);
            __nv_bfloat16 h3 = __float2bfloat16(e3);
            __nv_bfloat16 l0 = __float2bfloat16(e0 - __bfloat162float(h0));
            __nv_bfloat16 l1 = __float2bfloat16(e1 - __bfloat162float(h1));
            __nv_bfloat16 l2 = __float2bfloat16(e2 - __bfloat162float(h2));
            __nv_bfloat16 l3 = __float2bfloat16(e3 - __bfloat162float(h3));
            uint32_t o1 = (uint32_t)(row1 * 256 + ((nt ^ (row1 & 7)) << 4) + jj * 2);
            uint32_t o2 = (uint32_t)(row2 * 256 + ((nt ^ (row2 & 7)) << 4) + jj * 2);
            *(uint32_t*)(smem + AT_FHI + o1) = pack_bf2(h0, h1);
            *(uint32_t*)(smem + AT_FHI + o2) = pack_bf2(h2, h3);
            *(uint32_t*)(smem + AT_FLO + o1) = pack_bf2(l0, l1);
            *(uint32_t*)(smem + AT_FLO + o2) = pack_bf2(l2, l3);
        }
    }

    CP_WAIT(0);
    __syncthreads();

    // --- Phase 3: R = fin^T V (warps 0..6, j-tile = wid) ---
    if (wid < 7) {
        float racc[16][4];
#pragma unroll
        for (int nt = 0; nt < 16; nt++)
#pragma unroll
            for (int e = 0; e < 4; e++) racc[nt][e] = 0.f;

        int g = lane >> 3;
        int jc = 2 * wid;
        for (int ik = 0; ik < 7; ik++) {
            // A = fin^T fragments (trans ldsm on fin rows)
            uint32_t ah[4], al[4];
            {
                int r  = 16 * ik + ((g & 2) ? 8 : 0) + (lane & 7);
                int cc = jc + (g & 1);
                uint32_t off = (uint32_t)(r * 256 + ((cc ^ (r & 7)) << 4));
                ldsm_x4t(sbase + AT_FHI + off, ah);
                ldsm_x4t(sbase + AT_FLO + off, al);
            }
#pragma unroll
            for (int nt2 = 0; nt2 < 8; nt2++) {
                int r  = 16 * ik + ((g & 1) ? 8 : 0) + (lane & 7);
                int cc = 2 * nt2 + (g >> 1);
                uint32_t off = (uint32_t)(r * 256 + ((cc ^ (r & 7)) << 4));
                uint32_t vh[4], vl[4];
                ldsm_x4t(sbase + AT_VHI + off, vh);
                ldsm_x4t(sbase + AT_VLO + off, vl);
                uint32_t bh0[2] = {vh[0], vh[1]}, bh1[2] = {vh[2], vh[3]};
                uint32_t bl0[2] = {vl[0], vl[1]}, bl1[2] = {vl[2], vl[3]};
                mma_bf16(racc[2 * nt2],     ah, bh0);
                mma_bf16(racc[2 * nt2],     ah, bl0);
                mma_bf16(racc[2 * nt2],     al, bh0);
                mma_bf16(racc[2 * nt2 + 1], ah, bh1);
                mma_bf16(racc[2 * nt2 + 1], ah, bl1);
                mma_bf16(racc[2 * nt2 + 1], al, bh1);
            }
        }

        // epilogue: out = R / csum * ws + bs
        float ws = wsp[0], bs = bsp[0];
        int j1 = 16 * wid + (lane >> 2);
        int j2 = j1 + 8;
        float r1 = (j1 < 100) ? (1.f / csum[j1]) * ws : 0.f;
        float r2 = (j2 < 100) ? (1.f / csum[j2]) * ws : 0.f;
        float* orow1 = out + (size_t)(b * 100 + j1) * 2048 + h * 128;
        float* orow2 = out + (size_t)(b * 100 + j2) * 2048 + h * 128;
#pragma unroll
        for (int nt = 0; nt < 16; nt++) {
            int dv = nt * 8 + (lane & 3) * 2;
            if (j1 < 100) {
                float2 v; v.x = racc[nt][0] * r1 + bs; v.y = racc[nt][1] * r1 + bs;
                *(float2*)(orow1 + dv) = v;
            }
            if (j2 < 100) {
                float2 v; v.x = racc[nt][2] * r2 + bs; v.y = racc[nt][3] * r2 + bs;
                *(float2*)(orow2 + dv) = v;
            }
        }
    }
}

// ---------------------------------------------------------------------------
// Launcher
// ---------------------------------------------------------------------------
extern "C" void kernel_launch(void* const* d_in, const int* in_sizes, int n_in,
                              void* d_out, int out_size)
{
    const float* a_feat = (const float*)d_in[0];
    const float* g_feat = (const float*)d_in[1];
    const float* W_g    = (const float*)d_in[4];
    const float* b_g    = (const float*)d_in[5];
    const float* W_K    = (const float*)d_in[6];
    const float* b_K    = (const float*)d_in[7];
    const float* W_Q    = (const float*)d_in[8];
    const float* b_Q    = (const float*)d_in[9];
    const float* w_s    = (const float*)d_in[10];
    const float* b_s    = (const float*)d_in[11];
    float* out          = (float*)d_out;

    float *Kp, *Qp, *gwp;
    __nv_bfloat16 *Ahp, *Alp, *WKhp, *WKlp, *WQhp, *WQlp;
    cudaGetSymbolAddress((void**)&Kp,  g_K);
    cudaGetSymbolAddress((void**)&Qp,  g_Q);
    cudaGetSymbolAddress((void**)&gwp, g_gwT);
    cudaGetSymbolAddress((void**)&Ahp, g_Ahi);
    cudaGetSymbolAddress((void**)&Alp, g_Alo);
    cudaGetSymbolAddress((void**)&WKhp, g_WKhi);
    cudaGetSymbolAddress((void**)&WKlp, g_WKlo);
    cudaGetSymbolAddress((void**)&WQhp, g_WQhi);
    cudaGetSymbolAddress((void**)&WQlp, g_WQlo);

    // 1) fp32 -> bf16 hi/lo conversions
    conv_kernel<<<(P_ * D_) / 1024, 256>>>(a_feat, Ahp, Alp);
    conv_kernel<<<(D_ * KQ_COLS) / 1024, 256>>>(W_K, WKhp, WKlp);
    conv_kernel<<<(D_ * KQ_COLS) / 1024, 256>>>(W_Q, WQhp, WQlp);

    // 2) gate
    gate_kernel<<<PAIRS / 512, 256>>>(g_feat, W_g, b_g, gwp);

    // 3) K & Q GEMMs (mma.sync bf16 3-pass, 3-stage pipeline)
    cudaFuncSetAttribute(gemm_mma, cudaFuncAttributeMaxDynamicSharedMemorySize,
                         GEMM_SMEM);
    dim3 ggrid(KQ_COLS / 128, P_ / 128, 2);   // (8, 50, 2)
    gemm_mma<<<ggrid, 256, GEMM_SMEM>>>(Ahp, Alp, WKhp, WKlp, WQhp, WQlp,
                                        b_K, b_Q, Kp, Qp);

    // 4) tensor-core attention
    cudaFuncSetAttribute(attn_kernel, cudaFuncAttributeMaxDynamicSharedMemorySize,
                         ATTN_SMEM);
    dim3 agrid(NR_, B_);
    attn_kernel<<<agrid, 256, ATTN_SMEM>>>(Kp, Qp, gwp, Ahp, Alp, w_s, b_s, out);
}

// round 7
// speedup vs baseline: 1.0057x; 1.0057x over previous
#include <cuda_runtime.h>
#include <cuda_bf16.h>
#include <cstdint>

// Problem constants
#define B_   64
#define N_   100
#define D_   2048
#define NR_  16
#define DK_  64
#define DV_  128
#define P_   (B_*N_)          // 6400
#define KQ_COLS (NR_*DK_)     // 1024
#define PAIRS (B_*N_*N_)      // 640000

// ---------------------------------------------------------------------------
// Scratch (device globals; allocation APIs are forbidden)
// ---------------------------------------------------------------------------
__device__ float g_K[P_ * KQ_COLS];          // 6400 x 1024
__device__ float g_Q[P_ * KQ_COLS];          // 6400 x 1024
__device__ float g_gwT[B_ * NR_ * N_ * N_];  // [b][h][i*100+j]

__device__ __align__(16) __nv_bfloat16 g_Ahi[P_ * D_];        // [m][k]
__device__ __align__(16) __nv_bfloat16 g_Alo[P_ * D_];
__device__ __align__(16) __nv_bfloat16 g_WKhi[D_ * KQ_COLS];  // [k][n]
__device__ __align__(16) __nv_bfloat16 g_WKlo[D_ * KQ_COLS];
__device__ __align__(16) __nv_bfloat16 g_WQhi[D_ * KQ_COLS];
__device__ __align__(16) __nv_bfloat16 g_WQlo[D_ * KQ_COLS];

// ---------------------------------------------------------------------------
// PTX helpers (baseline ISA only: cp.async / ldmatrix / mma.sync)
// ---------------------------------------------------------------------------
__device__ __forceinline__ uint32_t smem_u32(const void* p) {
    uint32_t a;
    asm("{ .reg .u64 t; cvta.to.shared.u64 t, %1; cvt.u32.u64 %0, t; }"
        : "=r"(a) : "l"(p));
    return a;
}
__device__ __forceinline__ void cp_async16(uint32_t dst, const void* src) {
    asm volatile("cp.async.cg.shared.global [%0], [%1], 16;" :: "r"(dst), "l"(src));
}
#define CP_COMMIT() asm volatile("cp.async.commit_group;" ::: "memory")
#define CP_WAIT(n)  asm volatile("cp.async.wait_group %0;" :: "n"(n) : "memory")

__device__ __forceinline__ void ldsm_x4(uint32_t addr, uint32_t* f) {
    asm volatile("ldmatrix.sync.aligned.m8n8.x4.shared.b16 {%0,%1,%2,%3}, [%4];"
                 : "=r"(f[0]), "=r"(f[1]), "=r"(f[2]), "=r"(f[3]) : "r"(addr));
}
__device__ __forceinline__ void ldsm_x4t(uint32_t addr, uint32_t* f) {
    asm volatile("ldmatrix.sync.aligned.m8n8.x4.trans.shared.b16 {%0,%1,%2,%3}, [%4];"
                 : "=r"(f[0]), "=r"(f[1]), "=r"(f[2]), "=r"(f[3]) : "r"(addr));
}
__device__ __forceinline__ void mma_bf16(float* d, const uint32_t* a, const uint32_t* b) {
    asm volatile("mma.sync.aligned.m16n8k16.row.col.f32.bf16.bf16.f32 "
                 "{%0,%1,%2,%3}, {%4,%5,%6,%7}, {%8,%9}, {%0,%1,%2,%3};"
                 : "+f"(d[0]), "+f"(d[1]), "+f"(d[2]), "+f"(d[3])
                 : "r"(a[0]), "r"(a[1]), "r"(a[2]), "r"(a[3]),
                   "r"(b[0]), "r"(b[1]));
}

// ---------------------------------------------------------------------------
// Kernel 1: gate.  2 pairs per thread (R6 version — best measured).
// ---------------------------------------------------------------------------
__global__ __launch_bounds__(256) void gate_kernel(
    const float* __restrict__ G, const float* __restrict__ Wg,
    const float* __restrict__ bg, float* __restrict__ out)
{
    __shared__ float sW[64][16];
    __shared__ float sb[16];
    int tid = threadIdx.x;
    if (tid < 16) sb[tid] = bg[tid];
    for (int idx = tid; idx < 64 * 16; idx += 256)
        sW[idx >> 4][idx & 15] = Wg[idx];
    __syncthreads();

    int p0 = blockIdx.x * 512 + tid;   // pairs p0, p0+256

    float acc[2][16];
#pragma unroll
    for (int q = 0; q < 2; q++)
#pragma unroll
        for (int h = 0; h < 16; h++) acc[q][h] = sb[h];

    const float4* g4 = (const float4*)(G + (size_t)p0 * 64);

#pragma unroll 4
    for (int k4 = 0; k4 < 16; k4++) {
        float4 gv0 = g4[k4];
        float4 gv1 = g4[256 * 16 + k4];
#pragma unroll
        for (int e = 0; e < 4; e++) {
            int k = 4 * k4 + e;
            float4 w0 = *(const float4*)&sW[k][0];
            float4 w1 = *(const float4*)&sW[k][4];
            float4 w2 = *(const float4*)&sW[k][8];
            float4 w3 = *(const float4*)&sW[k][12];
            float wv[16] = {w0.x, w0.y, w0.z, w0.w, w1.x, w1.y, w1.z, w1.w,
                            w2.x, w2.y, w2.z, w2.w, w3.x, w3.y, w3.z, w3.w};
            float ge0 = (e == 0) ? gv0.x : (e == 1) ? gv0.y : (e == 2) ? gv0.z : gv0.w;
            float ge1 = (e == 0) ? gv1.x : (e == 1) ? gv1.y : (e == 2) ? gv1.z : gv1.w;
#pragma unroll
            for (int h = 0; h < 16; h++) {
                acc[0][h] += ge0 * wv[h];
                acc[1][h] += ge1 * wv[h];
            }
        }
    }

#pragma unroll
    for (int q = 0; q < 2; q++) {
        int p  = p0 + q * 256;
        int b  = p / (N_ * N_);
        int lp = p - b * (N_ * N_);
        float* ob = out + (size_t)b * (NR_ * N_ * N_) + lp;
#pragma unroll
        for (int h = 0; h < 16; h++)
            ob[(size_t)h * (N_ * N_)] = fmaxf(acc[q][h], 1e-6f);
    }
}

// ---------------------------------------------------------------------------
// Kernel 2: fp32 -> bf16 hi/lo (elementwise; used for A, W_K, W_Q)
// ---------------------------------------------------------------------------
__global__ __launch_bounds__(256) void conv_kernel(const float* __restrict__ X,
                                                   __nv_bfloat16* __restrict__ hi,
                                                   __nv_bfloat16* __restrict__ lo)
{
    int i = (blockIdx.x * 256 + threadIdx.x) * 4;
    float4 v = *(const float4*)(X + i);
    float xs[4] = {v.x, v.y, v.z, v.w};
    __nv_bfloat16 h[4], l[4];
#pragma unroll
    for (int e = 0; e < 4; e++) {
        h[e] = __float2bfloat16(xs[e]);
        l[e] = __float2bfloat16(xs[e] - __bfloat162float(h[e]));
    }
    *(__nv_bfloat162*)(hi + i)     = __nv_bfloat162(h[0], h[1]);
    *(__nv_bfloat162*)(hi + i + 2) = __nv_bfloat162(h[2], h[3]);
    *(__nv_bfloat162*)(lo + i)     = __nv_bfloat162(l[0], l[1]);
    *(__nv_bfloat162*)(lo + i + 2) = __nv_bfloat162(l[2], l[3]);
}

// ---------------------------------------------------------------------------
// Kernel 3: bf16 3-pass GEMM via mma.sync.  C[6400,1024] = A@W + bias
// 128x128 CTA tile, 16 warps (4x4), warp tile 32x32, K-chunk 64,
// 3-stage cp.async pipeline (192KB smem).  grid (8, 50, 2): z=0->K, z=1->Q.
// 512 threads: 4 warps/SMSP for latency hiding (R5 had 2).
//
// stage layout (64KB): Ahi[128][64] @0, Alo @16384, Whi[64][128] @32768,
// Wlo @49152.
// A swizzle: off = r*128 + ((cc ^ (r&7))<<4), cc = 16B k-chunk 0..7.
// W swizzle: off = k*256 + ((cc ^ (k&7))<<4), cc = 16B n-chunk 0..15.
// ---------------------------------------------------------------------------
#define KC 64
#define NCHUNKS (D_ / KC)        // 32
#define STAGEBYTES 65536
#define GEMM_SMEM (3 * STAGEBYTES)

__global__ __launch_bounds__(512, 1) void gemm_mma(
    const __nv_bfloat16* __restrict__ Ah, const __nv_bfloat16* __restrict__ Al,
    const __nv_bfloat16* __restrict__ WKh, const __nv_bfloat16* __restrict__ WKl,
    const __nv_bfloat16* __restrict__ WQh, const __nv_bfloat16* __restrict__ WQl,
    const float* __restrict__ bK, const float* __restrict__ bQ,
    float* __restrict__ gK, float* __restrict__ gQ)
{
    extern __shared__ char smem[];
    uint32_t sbase = smem_u32(smem);
    int tid = threadIdx.x;
    int wid = tid >> 5, lane = tid & 31;
    int wm = wid >> 2, wn = wid & 3;   // 4 x 4 warp grid, warp tile 32x32

    const __nv_bfloat16 *Wh, *Wl;
    const float* bias;
    float* C;
    if (blockIdx.z == 0) { Wh = WKh; Wl = WKl; bias = bK; C = gK; }
    else                 { Wh = WQh; Wl = WQl; bias = bQ; C = gQ; }

    int m0 = blockIdx.y * 128;
    int n0 = blockIdx.x * 128;

    float acc[2][4][4];
#pragma unroll
    for (int mi = 0; mi < 2; mi++)
#pragma unroll
        for (int nj = 0; nj < 4; nj++)
#pragma unroll
            for (int e = 0; e < 4; e++) acc[mi][nj][e] = 0.f;

    auto load_chunk = [&](int c, int s) {
        int k0 = c * KC;
        uint32_t base = sbase + s * STAGEBYTES;
#pragma unroll
        for (int t = 0; t < 2; t++) {
            const __nv_bfloat16* src = t ? Al : Ah;
#pragma unroll
            for (int l2 = 0; l2 < 2; l2++) {
                int id = tid + l2 * 512;        // 0..1023
                int r = id >> 3, cc = id & 7;
                cp_async16(base + t * 16384 + r * 128 + ((cc ^ (r & 7)) << 4),
                           src + (size_t)(m0 + r) * 2048 + k0 + cc * 8);
            }
        }
#pragma unroll
        for (int t = 0; t < 2; t++) {
            const __nv_bfloat16* src = t ? Wl : Wh;
#pragma unroll
            for (int l2 = 0; l2 < 2; l2++) {
                int id = tid + l2 * 512;
                int k = id >> 4, cc = id & 15;
                cp_async16(base + 32768 + t * 16384 + k * 256 + ((cc ^ (k & 7)) << 4),
                           src + (size_t)(k0 + k) * 1024 + n0 + cc * 8);
            }
        }
        CP_COMMIT();
    };

    load_chunk(0, 0);
    load_chunk(1, 1);
    load_chunk(2, 2);

    int ar  = lane & 15;          // A: row within 16-row block
    int acs = lane >> 4;          // A: k16-half select
    int wg8 = lane >> 3;          // W: 8-lane group 0..3
    int wk8 = lane & 7;
    int wks = (wg8 & 1) * 8;
    int wns = wg8 >> 1;

    int s = 0;
    for (int c = 0; c < NCHUNKS; c++) {
        CP_WAIT(2);
        __syncthreads();
        uint32_t base = sbase + s * STAGEBYTES;

#pragma unroll
        for (int ki = 0; ki < 4; ki++) {
            uint32_t afh[2][4], afl[2][4];
#pragma unroll
            for (int mi = 0; mi < 2; mi++) {
                int r = wm * 32 + mi * 16 + ar;
                int cc = 2 * ki + acs;
                uint32_t off = (uint32_t)(r * 128 + ((cc ^ (r & 7)) << 4));
                ldsm_x4(base + off, afh[mi]);
                ldsm_x4(base + 16384 + off, afl[mi]);
            }
            uint32_t bfh[4][2], bfl[4][2];
#pragma unroll
            for (int nh = 0; nh < 2; nh++) {
                int k  = ki * 16 + wks + wk8;
                int cc = wn * 4 + 2 * nh + wns;
                uint32_t off = (uint32_t)(k * 256 + ((cc ^ (k & 7)) << 4));
                uint32_t q[4];
                ldsm_x4t(base + 32768 + off, q);
                bfh[2 * nh][0] = q[0]; bfh[2 * nh][1] = q[1];
                bfh[2 * nh + 1][0] = q[2]; bfh[2 * nh + 1][1] = q[3];
                ldsm_x4t(base + 49152 + off, q);
                bfl[2 * nh][0] = q[0]; bfl[2 * nh][1] = q[1];
                bfl[2 * nh + 1][0] = q[2]; bfl[2 * nh + 1][1] = q[3];
            }
#pragma unroll
            for (int mi = 0; mi < 2; mi++)
#pragma unroll
                for (int nj = 0; nj < 4; nj++) {
                    mma_bf16(acc[mi][nj], afh[mi], bfh[nj]);
                    mma_bf16(acc[mi][nj], afh[mi], bfl[nj]);
                    mma_bf16(acc[mi][nj], afl[mi], bfh[nj]);
                }
        }
        __syncthreads();
        if (c + 3 < NCHUNKS) load_chunk(c + 3, s); else CP_COMMIT();
        s = (s == 2) ? 0 : s + 1;
    }

    // ---- epilogue: add bias, store fp32 ----
    int g = lane >> 2, t4 = lane & 3;
    float bcol[4][2];
#pragma unroll
    for (int nj = 0; nj < 4; nj++) {
        int col = n0 + wn * 32 + nj * 8 + t4 * 2;
        bcol[nj][0] = __ldg(bias + col);
        bcol[nj][1] = __ldg(bias + col + 1);
    }
#pragma unroll
    for (int mi = 0; mi < 2; mi++) {
#pragma unroll
        for (int half = 0; half < 2; half++) {
            int m = m0 + wm * 32 + mi * 16 + g + half * 8;
            float* crow = C + (size_t)m * 1024 + n0 + wn * 32;
#pragma unroll
            for (int nj = 0; nj < 4; nj++) {
                int col = nj * 8 + t4 * 2;
                float2 v;
                v.x = acc[mi][nj][half * 2 + 0] + bcol[nj][0];
                v.y = acc[mi][nj][half * 2 + 1] + bcol[nj][1];
                *(float2*)(crow + col) = v;
            }
        }
    }
}

// ---------------------------------------------------------------------------
// Kernel 4: per (b,h) SIMT attention (R5 version — best measured).
// ---------------------------------------------------------------------------
#define KQPAD 65
#define FINPAD 112

__global__ __launch_bounds__(256) void attn_kernel(
    const float* __restrict__ Kmat, const float* __restrict__ Qmat,
    const float* __restrict__ gw, const float* __restrict__ A,
    const float* __restrict__ wsp, const float* __restrict__ bsp,
    float* __restrict__ out)
{
    extern __shared__ float sm[];
    float* Ks  = sm;
    float* Qs  = sm + 112 * KQPAD;
    float* Vs  = sm;
    float* fin = sm + 2 * 112 * KQPAD;
    float* csum = fin + 100 * FINPAD;

    int h = blockIdx.x;
    int b = blockIdx.y;
    int tid = threadIdx.x;
    int tx = tid & 15, ty = tid >> 4;

    for (int idx = tid; idx < 112 * 64; idx += 256) {
        int i = idx >> 6, d = idx & 63;
        float kv = 0.f, qv = 0.f;
        if (i < 100) {
            size_t gofs = (size_t)(b * 100 + i) * 1024 + h * 64 + d;
            kv = Kmat[gofs];
            qv = Qmat[gofs];
        }
        Ks[i * KQPAD + d] = kv;
        Qs[i * KQPAD + d] = qv;
    }
    __syncthreads();

    const float* gwb = gw + ((size_t)(b * 16 + h)) * 10000;
    {
        float acc[7][7];
#pragma unroll
        for (int ii = 0; ii < 7; ii++)
#pragma unroll
            for (int jj = 0; jj < 7; jj++) acc[ii][jj] = 0.f;

        for (int d = 0; d < 64; d++) {
            float kk[7], qq[7];
#pragma unroll
            for (int ii = 0; ii < 7; ii++) kk[ii] = Ks[(ty + 16 * ii) * KQPAD + d];
#pragma unroll
            for (int jj = 0; jj < 7; jj++) qq[jj] = Qs[(tx + 16 * jj) * KQPAD + d];
#pragma unroll
            for (int ii = 0; ii < 7; ii++)
#pragma unroll
                for (int jj = 0; jj < 7; jj++)
                    acc[ii][jj] += kk[ii] * qq[jj];
        }
#pragma unroll
        for (int ii = 0; ii < 7; ii++) {
            int i = ty + 16 * ii;
            if (i >= 100) continue;
#pragma unroll
            for (int jj = 0; jj < 7; jj++) {
                int j = tx + 16 * jj;
                if (j >= 100) continue;
                float e = gwb[i * 100 + j] * __expf(acc[ii][jj] * 0.125f);
                fin[i * FINPAD + j] = e;
            }
        }
    }
    __syncthreads();

    if (tid < 100) {
        float ssum = 0.f;
        for (int i = 0; i < 100; i++) ssum += fin[i * FINPAD + tid];
        csum[tid] = 1.f / ssum;
    }
    for (int idx = tid; idx < 100 * 128; idx += 256) {
        int i = idx >> 7, d = idx & 127;
        Vs[idx] = A[(size_t)(b * 100 + i) * 2048 + h * 128 + d];
    }
    __syncthreads();

    float ws = wsp[0], bs = bsp[0];
    float r[7][8];
#pragma unroll
    for (int jj = 0; jj < 7; jj++)
#pragma unroll
        for (int dd = 0; dd < 8; dd++) r[jj][dd] = 0.f;

    for (int i = 0; i < 100; i++) {
        float vv[8], ff[7];
#pragma unroll
        for (int dd = 0; dd < 8; dd++) vv[dd] = Vs[i * 128 + tx + 16 * dd];
#pragma unroll
        for (int jj = 0; jj < 7; jj++) ff[jj] = fin[i * FINPAD + ty + 16 * jj];
#pragma unroll
        for (int jj = 0; jj < 7; jj++)
#pragma unroll
            for (int dd = 0; dd < 8; dd++)
                r[jj][dd] += vv[dd] * ff[jj];
    }

#pragma unroll
    for (int jj = 0; jj < 7; jj++) {
        int j = ty + 16 * jj;
        if (j >= 100) continue;
        float rc = csum[j];
        float* orow = out + (size_t)(b * 100 + j) * 2048 + h * 128;
#pragma unroll
        for (int dd = 0; dd < 8; dd++) {
            int d = tx + 16 * dd;
            orow[d] = (r[jj][dd] * rc) * ws + bs;
        }
    }
}

// ---------------------------------------------------------------------------
// Launcher
// ---------------------------------------------------------------------------
extern "C" void kernel_launch(void* const* d_in, const int* in_sizes, int n_in,
                              void* d_out, int out_size)
{
    const float* a_feat = (const float*)d_in[0];
    const float* g_feat = (const float*)d_in[1];
    const float* W_g    = (const float*)d_in[4];
    const float* b_g    = (const float*)d_in[5];
    const float* W_K    = (const float*)d_in[6];
    const float* b_K    = (const float*)d_in[7];
    const float* W_Q    = (const float*)d_in[8];
    const float* b_Q    = (const float*)d_in[9];
    const float* w_s    = (const float*)d_in[10];
    const float* b_s    = (const float*)d_in[11];
    float* out          = (float*)d_out;

    float *Kp, *Qp, *gwp;
    __nv_bfloat16 *Ahp, *Alp, *WKhp, *WKlp, *WQhp, *WQlp;
    cudaGetSymbolAddress((void**)&Kp,  g_K);
    cudaGetSymbolAddress((void**)&Qp,  g_Q);
    cudaGetSymbolAddress((void**)&gwp, g_gwT);
    cudaGetSymbolAddress((void**)&Ahp, g_Ahi);
    cudaGetSymbolAddress((void**)&Alp, g_Alo);
    cudaGetSymbolAddress((void**)&WKhp, g_WKhi);
    cudaGetSymbolAddress((void**)&WKlp, g_WKlo);
    cudaGetSymbolAddress((void**)&WQhp, g_WQhi);
    cudaGetSymbolAddress((void**)&WQlp, g_WQlo);

    // 1) fp32 -> bf16 hi/lo conversions
    conv_kernel<<<(P_ * D_) / 1024, 256>>>(a_feat, Ahp, Alp);
    conv_kernel<<<(D_ * KQ_COLS) / 1024, 256>>>(W_K, WKhp, WKlp);
    conv_kernel<<<(D_ * KQ_COLS) / 1024, 256>>>(W_Q, WQhp, WQlp);

    // 2) gate
    gate_kernel<<<PAIRS / 512, 256>>>(g_feat, W_g, b_g, gwp);

    // 3) K & Q GEMMs (mma.sync bf16 3-pass, 3-stage pipeline, 512 threads)
    cudaFuncSetAttribute(gemm_mma, cudaFuncAttributeMaxDynamicSharedMemorySize,
                         GEMM_SMEM);
    dim3 ggrid(KQ_COLS / 128, P_ / 128, 2);   // (8, 50, 2)
    gemm_mma<<<ggrid, 512, GEMM_SMEM>>>(Ahp, Alp, WKhp, WKlp, WQhp, WQlp,
                                        b_K, b_Q, Kp, Qp);

    // 4) SIMT attention
    int smem_bytes = (2 * 112 * KQPAD + 100 * FINPAD + 100) * (int)sizeof(float);
    cudaFuncSetAttribute(attn_kernel, cudaFuncAttributeMaxDynamicSharedMemorySize,
                         smem_bytes);
    dim3 agrid(NR_, B_);
    attn_kernel<<<agrid, 256, smem_bytes>>>(Kp, Qp, gwp, a_feat, w_s, b_s, out);
}

// round 8
// speedup vs baseline: 1.1149x; 1.1085x over previous
#include <cuda_runtime.h>
#include <cuda_bf16.h>
#include <cstdint>

// Problem constants
#define B_   64
#define N_   100
#define D_   2048
#define NR_  16
#define DK_  64
#define DV_  128
#define P_   (B_*N_)          // 6400
#define KQ_COLS (NR_*DK_)     // 1024
#define PAIRS (B_*N_*N_)      // 640000

// ---------------------------------------------------------------------------
// Scratch (device globals; allocation APIs are forbidden)
// ---------------------------------------------------------------------------
__device__ float g_K[P_ * KQ_COLS];          // 6400 x 1024
__device__ float g_Q[P_ * KQ_COLS];          // 6400 x 1024
__device__ float g_gwT[B_ * NR_ * N_ * N_];  // [b][h][i*100+j]

__device__ __align__(16) __nv_bfloat16 g_Ahi[P_ * D_];        // [m][k]
__device__ __align__(16) __nv_bfloat16 g_Alo[P_ * D_];
__device__ __align__(16) __nv_bfloat16 g_WKhi[D_ * KQ_COLS];  // [k][n]
__device__ __align__(16) __nv_bfloat16 g_WKlo[D_ * KQ_COLS];
__device__ __align__(16) __nv_bfloat16 g_WQhi[D_ * KQ_COLS];
__device__ __align__(16) __nv_bfloat16 g_WQlo[D_ * KQ_COLS];

// ---------------------------------------------------------------------------
// PTX helpers (baseline ISA only: cp.async / ldmatrix / mma.sync)
// ---------------------------------------------------------------------------
__device__ __forceinline__ uint32_t smem_u32(const void* p) {
    uint32_t a;
    asm("{ .reg .u64 t; cvta.to.shared.u64 t, %1; cvt.u32.u64 %0, t; }"
        : "=r"(a) : "l"(p));
    return a;
}
__device__ __forceinline__ void cp_async16(uint32_t dst, const void* src) {
    asm volatile("cp.async.cg.shared.global [%0], [%1], 16;" :: "r"(dst), "l"(src));
}
#define CP_COMMIT() asm volatile("cp.async.commit_group;" ::: "memory")
#define CP_WAIT(n)  asm volatile("cp.async.wait_group %0;" :: "n"(n) : "memory")

__device__ __forceinline__ void ldsm_x4(uint32_t addr, uint32_t* f) {
    asm volatile("ldmatrix.sync.aligned.m8n8.x4.shared.b16 {%0,%1,%2,%3}, [%4];"
                 : "=r"(f[0]), "=r"(f[1]), "=r"(f[2]), "=r"(f[3]) : "r"(addr));
}
__device__ __forceinline__ void ldsm_x4t(uint32_t addr, uint32_t* f) {
    asm volatile("ldmatrix.sync.aligned.m8n8.x4.trans.shared.b16 {%0,%1,%2,%3}, [%4];"
                 : "=r"(f[0]), "=r"(f[1]), "=r"(f[2]), "=r"(f[3]) : "r"(addr));
}
__device__ __forceinline__ void mma_bf16(float* d, const uint32_t* a, const uint32_t* b) {
    asm volatile("mma.sync.aligned.m16n8k16.row.col.f32.bf16.bf16.f32 "
                 "{%0,%1,%2,%3}, {%4,%5,%6,%7}, {%8,%9}, {%0,%1,%2,%3};"
                 : "+f"(d[0]), "+f"(d[1]), "+f"(d[2]), "+f"(d[3])
                 : "r"(a[0]), "r"(a[1]), "r"(a[2]), "r"(a[3]),
                   "r"(b[0]), "r"(b[1]));
}

// ---------------------------------------------------------------------------
// Kernel 1: gate.  2 pairs per thread (best measured).
// ---------------------------------------------------------------------------
__global__ __launch_bounds__(256) void gate_kernel(
    const float* __restrict__ G, const float* __restrict__ Wg,
    const float* __restrict__ bg, float* __restrict__ out)
{
    __shared__ float sW[64][16];
    __shared__ float sb[16];
    int tid = threadIdx.x;
    if (tid < 16) sb[tid] = bg[tid];
    for (int idx = tid; idx < 64 * 16; idx += 256)
        sW[idx >> 4][idx & 15] = Wg[idx];
    __syncthreads();

    int p0 = blockIdx.x * 512 + tid;

    float acc[2][16];
#pragma unroll
    for (int q = 0; q < 2; q++)
#pragma unroll
        for (int h = 0; h < 16; h++) acc[q][h] = sb[h];

    const float4* g4 = (const float4*)(G + (size_t)p0 * 64);

#pragma unroll 4
    for (int k4 = 0; k4 < 16; k4++) {
        float4 gv0 = g4[k4];
        float4 gv1 = g4[256 * 16 + k4];
#pragma unroll
        for (int e = 0; e < 4; e++) {
            int k = 4 * k4 + e;
            float4 w0 = *(const float4*)&sW[k][0];
            float4 w1 = *(const float4*)&sW[k][4];
            float4 w2 = *(const float4*)&sW[k][8];
            float4 w3 = *(const float4*)&sW[k][12];
            float wv[16] = {w0.x, w0.y, w0.z, w0.w, w1.x, w1.y, w1.z, w1.w,
                            w2.x, w2.y, w2.z, w2.w, w3.x, w3.y, w3.z, w3.w};
            float ge0 = (e == 0) ? gv0.x : (e == 1) ? gv0.y : (e == 2) ? gv0.z : gv0.w;
            float ge1 = (e == 0) ? gv1.x : (e == 1) ? gv1.y : (e == 2) ? gv1.z : gv1.w;
#pragma unroll
            for (int h = 0; h < 16; h++) {
                acc[0][h] += ge0 * wv[h];
                acc[1][h] += ge1 * wv[h];
            }
        }
    }

#pragma unroll
    for (int q = 0; q < 2; q++) {
        int p  = p0 + q * 256;
        int b  = p / (N_ * N_);
        int lp = p - b * (N_ * N_);
        float* ob = out + (size_t)b * (NR_ * N_ * N_) + lp;
#pragma unroll
        for (int h = 0; h < 16; h++)
            ob[(size_t)h * (N_ * N_)] = fmaxf(acc[q][h], 1e-6f);
    }
}

// ---------------------------------------------------------------------------
// Kernel 2: fp32 -> bf16 hi/lo for A, W_K, W_Q in ONE launch.
// blocks: [0,12800) A ; [12800,14848) W_K ; [14848,16896) W_Q
// ---------------------------------------------------------------------------
__global__ __launch_bounds__(256) void conv_all_kernel(
    const float* __restrict__ A, const float* __restrict__ WK,
    const float* __restrict__ WQ,
    __nv_bfloat16* __restrict__ Ah, __nv_bfloat16* __restrict__ Al,
    __nv_bfloat16* __restrict__ WKh, __nv_bfloat16* __restrict__ WKl,
    __nv_bfloat16* __restrict__ WQh, __nv_bfloat16* __restrict__ WQl)
{
    int bx = blockIdx.x;
    const float* X;
    __nv_bfloat16 *hi, *lo;
    int seg;
    if (bx < 12800)      { X = A;  hi = Ah;  lo = Al;  seg = bx; }
    else if (bx < 14848) { X = WK; hi = WKh; lo = WKl; seg = bx - 12800; }
    else                 { X = WQ; hi = WQh; lo = WQl; seg = bx - 14848; }

    size_t i = ((size_t)seg * 256 + threadIdx.x) * 4;
    float4 v = *(const float4*)(X + i);
    float xs[4] = {v.x, v.y, v.z, v.w};
    __nv_bfloat16 h[4], l[4];
#pragma unroll
    for (int e = 0; e < 4; e++) {
        h[e] = __float2bfloat16(xs[e]);
        l[e] = __float2bfloat16(xs[e] - __bfloat162float(h[e]));
    }
    *(__nv_bfloat162*)(hi + i)     = __nv_bfloat162(h[0], h[1]);
    *(__nv_bfloat162*)(hi + i + 2) = __nv_bfloat162(h[2], h[3]);
    *(__nv_bfloat162*)(lo + i)     = __nv_bfloat162(l[0], l[1]);
    *(__nv_bfloat162*)(lo + i + 2) = __nv_bfloat162(l[2], l[3]);
}

// ---------------------------------------------------------------------------
// Kernel 3: bf16 3-pass GEMM via mma.sync.  C[6400,1024] = A@W + bias
// CTA tile 256x128, 8 warps (4x2), warp tile 64x64, KC=64, 2-stage pipeline.
// grid (8, 25, 2): z=0->K, z=1->Q.
//
// stage layout (96KB): Ahi[256][64] @0 (32KB), Alo @32768,
//                      Whi[64][128] @65536 (16KB), Wlo @81920.
// A swizzle: off = r*128 + ((cc ^ (r&7))<<4), cc = 16B k-chunk 0..7.
// W swizzle: off = k*256 + ((cc ^ (k&7))<<4), cc = 16B n-chunk 0..15.
// ---------------------------------------------------------------------------
#define KC 64
#define NCHUNKS (D_ / KC)        // 32
#define STAGEBYTES 98304
#define GEMM_SMEM (2 * STAGEBYTES)

__global__ __launch_bounds__(256, 1) void gemm_mma(
    const __nv_bfloat16* __restrict__ Ah, const __nv_bfloat16* __restrict__ Al,
    const __nv_bfloat16* __restrict__ WKh, const __nv_bfloat16* __restrict__ WKl,
    const __nv_bfloat16* __restrict__ WQh, const __nv_bfloat16* __restrict__ WQl,
    const float* __restrict__ bK, const float* __restrict__ bQ,
    float* __restrict__ gK, float* __restrict__ gQ)
{
    extern __shared__ char smem[];
    uint32_t sbase = smem_u32(smem);
    int tid = threadIdx.x;
    int wid = tid >> 5, lane = tid & 31;
    int wm = wid >> 1, wn = wid & 1;   // 4 x 2 warp grid, warp tile 64x64

    const __nv_bfloat16 *Wh, *Wl;
    const float* bias;
    float* C;
    if (blockIdx.z == 0) { Wh = WKh; Wl = WKl; bias = bK; C = gK; }
    else                 { Wh = WQh; Wl = WQl; bias = bQ; C = gQ; }

    int m0 = blockIdx.y * 256;
    int n0 = blockIdx.x * 128;

    float acc[4][8][4];
#pragma unroll
    for (int mi = 0; mi < 4; mi++)
#pragma unroll
        for (int nj = 0; nj < 8; nj++)
#pragma unroll
            for (int e = 0; e < 4; e++) acc[mi][nj][e] = 0.f;

    // ---- async load of one K-chunk into stage s ----
    auto load_chunk = [&](int c, int s) {
        int k0 = c * KC;
        uint32_t base = sbase + s * STAGEBYTES;
        // A hi/lo: 256 rows x 64 k = 128B rows, 2048 chunks of 16B each
#pragma unroll
        for (int t = 0; t < 2; t++) {
            const __nv_bfloat16* src = t ? Al : Ah;
#pragma unroll
            for (int l2 = 0; l2 < 8; l2++) {
                int id = tid + l2 * 256;        // 0..2047
                int r = id >> 3, cc = id & 7;
                cp_async16(base + t * 32768 + r * 128 + ((cc ^ (r & 7)) << 4),
                           src + (size_t)(m0 + r) * 2048 + k0 + cc * 8);
            }
        }
        // W hi/lo: 64 k-rows x 128 n = 256B rows, 1024 chunks
#pragma unroll
        for (int t = 0; t < 2; t++) {
            const __nv_bfloat16* src = t ? Wl : Wh;
#pragma unroll
            for (int l2 = 0; l2 < 4; l2++) {
                int id = tid + l2 * 256;
                int k = id >> 4, cc = id & 15;
                cp_async16(base + 65536 + t * 16384 + k * 256 + ((cc ^ (k & 7)) << 4),
                           src + (size_t)(k0 + k) * 1024 + n0 + cc * 8);
            }
        }
        CP_COMMIT();
    };

    load_chunk(0, 0);
    load_chunk(1, 1);

    // ldmatrix lane address components
    int ar  = lane & 15;          // A: row within 16-row block
    int acs = lane >> 4;          // A: k16-half select
    int wg8 = lane >> 3;          // W: 8-lane group 0..3
    int wk8 = lane & 7;
    int wks = (wg8 & 1) * 8;
    int wns = wg8 >> 1;

    for (int c = 0; c < NCHUNKS; c++) {
        CP_WAIT(1);
        __syncthreads();
        uint32_t base = sbase + (c & 1) * STAGEBYTES;

#pragma unroll
        for (int ki = 0; ki < 4; ki++) {
            uint32_t afh[4][4], afl[4][4];
#pragma unroll
            for (int mi = 0; mi < 4; mi++) {
                int r = wm * 64 + mi * 16 + ar;
                int cc = 2 * ki + acs;
                uint32_t off = (uint32_t)(r * 128 + ((cc ^ (r & 7)) << 4));
                ldsm_x4(base + off, afh[mi]);
                ldsm_x4(base + 32768 + off, afl[mi]);
            }
#pragma unroll
            for (int np = 0; np < 4; np++) {
                int k  = ki * 16 + wks + wk8;
                int cc = wn * 8 + 2 * np + wns;
                uint32_t off = (uint32_t)(k * 256 + ((cc ^ (k & 7)) << 4));
                uint32_t qh[4], ql[4];
                ldsm_x4t(base + 65536 + off, qh);
                ldsm_x4t(base + 81920 + off, ql);
                uint32_t bh0[2] = {qh[0], qh[1]}, bh1[2] = {qh[2], qh[3]};
                uint32_t bl0[2] = {ql[0], ql[1]}, bl1[2] = {ql[2], ql[3]};
#pragma unroll
                for (int mi = 0; mi < 4; mi++) {
                    mma_bf16(acc[mi][2 * np],     afh[mi], bh0);
                    mma_bf16(acc[mi][2 * np],     afh[mi], bl0);
                    mma_bf16(acc[mi][2 * np],     afl[mi], bh0);
                    mma_bf16(acc[mi][2 * np + 1], afh[mi], bh1);
                    mma_bf16(acc[mi][2 * np + 1], afh[mi], bl1);
                    mma_bf16(acc[mi][2 * np + 1], afl[mi], bh1);
                }
            }
        }
        __syncthreads();
        if (c + 2 < NCHUNKS) load_chunk(c + 2, c & 1); else CP_COMMIT();
    }

    // ---- epilogue: add bias, store fp32 ----
    int g = lane >> 2, t4 = lane & 3;
    float bcol[8][2];
#pragma unroll
    for (int nj = 0; nj < 8; nj++) {
        int col = n0 + wn * 64 + nj * 8 + t4 * 2;
        bcol[nj][0] = __ldg(bias + col);
        bcol[nj][1] = __ldg(bias + col + 1);
    }
#pragma unroll
    for (int mi = 0; mi < 4; mi++) {
#pragma unroll
        for (int half = 0; half < 2; half++) {
            int m = m0 + wm * 64 + mi * 16 + g + half * 8;
            float* crow = C + (size_t)m * 1024 + n0 + wn * 64;
#pragma unroll
            for (int nj = 0; nj < 8; nj++) {
                int col = nj * 8 + t4 * 2;
                float2 v;
                v.x = acc[mi][nj][half * 2 + 0] + bcol[nj][0];
                v.y = acc[mi][nj][half * 2 + 1] + bcol[nj][1];
                *(float2*)(crow + col) = v;
            }
        }
    }
}

// ---------------------------------------------------------------------------
// Kernel 4: per (b,h) SIMT attention (R5 version — best measured).
// ---------------------------------------------------------------------------
#define KQPAD 65
#define FINPAD 112

__global__ __launch_bounds__(256) void attn_kernel(
    const float* __restrict__ Kmat, const float* __restrict__ Qmat,
    const float* __restrict__ gw, const float* __restrict__ A,
    const float* __restrict__ wsp, const float* __restrict__ bsp,
    float* __restrict__ out)
{
    extern __shared__ float sm[];
    float* Ks  = sm;
    float* Qs  = sm + 112 * KQPAD;
    float* Vs  = sm;
    float* fin = sm + 2 * 112 * KQPAD;
    float* csum = fin + 100 * FINPAD;

    int h = blockIdx.x;
    int b = blockIdx.y;
    int tid = threadIdx.x;
    int tx = tid & 15, ty = tid >> 4;

    for (int idx = tid; idx < 112 * 64; idx += 256) {
        int i = idx >> 6, d = idx & 63;
        float kv = 0.f, qv = 0.f;
        if (i < 100) {
            size_t gofs = (size_t)(b * 100 + i) * 1024 + h * 64 + d;
            kv = Kmat[gofs];
            qv = Qmat[gofs];
        }
        Ks[i * KQPAD + d] = kv;
        Qs[i * KQPAD + d] = qv;
    }
    __syncthreads();

    const float* gwb = gw + ((size_t)(b * 16 + h)) * 10000;
    {
        float acc[7][7];
#pragma unroll
        for (int ii = 0; ii < 7; ii++)
#pragma unroll
            for (int jj = 0; jj < 7; jj++) acc[ii][jj] = 0.f;

        for (int d = 0; d < 64; d++) {
            float kk[7], qq[7];
#pragma unroll
            for (int ii = 0; ii < 7; ii++) kk[ii] = Ks[(ty + 16 * ii) * KQPAD + d];
#pragma unroll
            for (int jj = 0; jj < 7; jj++) qq[jj] = Qs[(tx + 16 * jj) * KQPAD + d];
#pragma unroll
            for (int ii = 0; ii < 7; ii++)
#pragma unroll
                for (int jj = 0; jj < 7; jj++)
                    acc[ii][jj] += kk[ii] * qq[jj];
        }
#pragma unroll
        for (int ii = 0; ii < 7; ii++) {
            int i = ty + 16 * ii;
            if (i >= 100) continue;
#pragma unroll
            for (int jj = 0; jj < 7; jj++) {
                int j = tx + 16 * jj;
                if (j >= 100) continue;
                float e = gwb[i * 100 + j] * __expf(acc[ii][jj] * 0.125f);
                fin[i * FINPAD + j] = e;
            }
        }
    }
    __syncthreads();

    if (tid < 100) {
        float ssum = 0.f;
        for (int i = 0; i < 100; i++) ssum += fin[i * FINPAD + tid];
        csum[tid] = 1.f / ssum;
    }
    for (int idx = tid; idx < 100 * 128; idx += 256) {
        int i = idx >> 7, d = idx & 127;
        Vs[idx] = A[(size_t)(b * 100 + i) * 2048 + h * 128 + d];
    }
    __syncthreads();

    float ws = wsp[0], bs = bsp[0];
    float r[7][8];
#pragma unroll
    for (int jj = 0; jj < 7; jj++)
#pragma unroll
        for (int dd = 0; dd < 8; dd++) r[jj][dd] = 0.f;

    for (int i = 0; i < 100; i++) {
        float vv[8], ff[7];
#pragma unroll
        for (int dd = 0; dd < 8; dd++) vv[dd] = Vs[i * 128 + tx + 16 * dd];
#pragma unroll
        for (int jj = 0; jj < 7; jj++) ff[jj] = fin[i * FINPAD + ty + 16 * jj];
#pragma unroll
        for (int jj = 0; jj < 7; jj++)
#pragma unroll
            for (int dd = 0; dd < 8; dd++)
                r[jj][dd] += vv[dd] * ff[jj];
    }

#pragma unroll
    for (int jj = 0; jj < 7; jj++) {
        int j = ty + 16 * jj;
        if (j >= 100) continue;
        float rc = csum[j];
        float* orow = out + (size_t)(b * 100 + j) * 2048 + h * 128;
#pragma unroll
        for (int dd = 0; dd < 8; dd++) {
            int d = tx + 16 * dd;
            orow[d] = (r[jj][dd] * rc) * ws + bs;
        }
    }
}

// ---------------------------------------------------------------------------
// Launcher
// ---------------------------------------------------------------------------
extern "C" void kernel_launch(void* const* d_in, const int* in_sizes, int n_in,
                              void* d_out, int out_size)
{
    const float* a_feat = (const float*)d_in[0];
    const float* g_feat = (const float*)d_in[1];
    const float* W_g    = (const float*)d_in[4];
    const float* b_g    = (const float*)d_in[5];
    const float* W_K    = (const float*)d_in[6];
    const float* b_K    = (const float*)d_in[7];
    const float* W_Q    = (const float*)d_in[8];
    const float* b_Q    = (const float*)d_in[9];
    const float* w_s    = (const float*)d_in[10];
    const float* b_s    = (const float*)d_in[11];
    float* out          = (float*)d_out;

    float *Kp, *Qp, *gwp;
    __nv_bfloat16 *Ahp, *Alp, *WKhp, *WKlp, *WQhp, *WQlp;
    cudaGetSymbolAddress((void**)&Kp,  g_K);
    cudaGetSymbolAddress((void**)&Qp,  g_Q);
    cudaGetSymbolAddress((void**)&gwp, g_gwT);
    cudaGetSymbolAddress((void**)&Ahp, g_Ahi);
    cudaGetSymbolAddress((void**)&Alp, g_Alo);
    cudaGetSymbolAddress((void**)&WKhp, g_WKhi);
    cudaGetSymbolAddress((void**)&WKlp, g_WKlo);
    cudaGetSymbolAddress((void**)&WQhp, g_WQhi);
    cudaGetSymbolAddress((void**)&WQlp, g_WQlo);

    // 1) fp32 -> bf16 hi/lo conversions (single launch)
    conv_all_kernel<<<16896, 256>>>(a_feat, W_K, W_Q,
                                    Ahp, Alp, WKhp, WKlp, WQhp, WQlp);

    // 2) gate
    gate_kernel<<<PAIRS / 512, 256>>>(g_feat, W_g, b_g, gwp);

    // 3) K & Q GEMMs (mma.sync bf16 3-pass, 256x128 CTA tile, 64x64 warp tile)
    cudaFuncSetAttribute(gemm_mma, cudaFuncAttributeMaxDynamicSharedMemorySize,
                         GEMM_SMEM);
    dim3 ggrid(KQ_COLS / 128, P_ / 256, 2);   // (8, 25, 2)
    gemm_mma<<<ggrid, 256, GEMM_SMEM>>>(Ahp, Alp, WKhp, WKlp, WQhp, WQlp,
                                        b_K, b_Q, Kp, Qp);

    // 4) SIMT attention
    int smem_bytes = (2 * 112 * KQPAD + 100 * FINPAD + 100) * (int)sizeof(float);
    cudaFuncSetAttribute(attn_kernel, cudaFuncAttributeMaxDynamicSharedMemorySize,
                         smem_bytes);
    dim3 agrid(NR_, B_);
    attn_kernel<<<agrid, 256, smem_bytes>>>(Kp, Qp, gwp, a_feat, w_s, b_s, out);
}

// round 11
// speedup vs baseline: 1.1558x; 1.0367x over previous
#include <cuda_runtime.h>
#include <cuda_bf16.h>
#include <cstdint>

// Problem constants
#define B_   64
#define N_   100
#define D_   2048
#define NR_  16
#define DK_  64
#define DV_  128
#define P_   (B_*N_)          // 6400
#define KQ_COLS (NR_*DK_)     // 1024
#define PAIRS (B_*N_*N_)      // 640000

// ---------------------------------------------------------------------------
// Scratch (device globals; allocation APIs are forbidden)
// ---------------------------------------------------------------------------
__device__ float g_K[P_ * KQ_COLS];          // 6400 x 1024
__device__ float g_Q[P_ * KQ_COLS];          // 6400 x 1024
__device__ float g_gwT[B_ * NR_ * N_ * N_];  // [b][h][i*100+j]; e overwrites gw

__device__ __align__(16) __nv_bfloat16 g_Ahi[P_ * D_];        // [m][k]
__device__ __align__(16) __nv_bfloat16 g_Alo[P_ * D_];
__device__ __align__(16) __nv_bfloat16 g_WKhi[D_ * KQ_COLS];  // [k][n]
__device__ __align__(16) __nv_bfloat16 g_WKlo[D_ * KQ_COLS];
__device__ __align__(16) __nv_bfloat16 g_WQhi[D_ * KQ_COLS];
__device__ __align__(16) __nv_bfloat16 g_WQlo[D_ * KQ_COLS];

// ---------------------------------------------------------------------------
// PTX helpers (baseline ISA only: cp.async / ldmatrix / mma.sync)
// ---------------------------------------------------------------------------
__device__ __forceinline__ uint32_t smem_u32(const void* p) {
    uint32_t a;
    asm("{ .reg .u64 t; cvta.to.shared.u64 t, %1; cvt.u32.u64 %0, t; }"
        : "=r"(a) : "l"(p));
    return a;
}
__device__ __forceinline__ void cp_async16(uint32_t dst, const void* src) {
    asm volatile("cp.async.cg.shared.global [%0], [%1], 16;" :: "r"(dst), "l"(src));
}
#define CP_COMMIT() asm volatile("cp.async.commit_group;" ::: "memory")
#define CP_WAIT(n)  asm volatile("cp.async.wait_group %0;" :: "n"(n) : "memory")

__device__ __forceinline__ void ldsm_x4(uint32_t addr, uint32_t* f) {
    asm volatile("ldmatrix.sync.aligned.m8n8.x4.shared.b16 {%0,%1,%2,%3}, [%4];"
                 : "=r"(f[0]), "=r"(f[1]), "=r"(f[2]), "=r"(f[3]) : "r"(addr));
}
__device__ __forceinline__ void ldsm_x4t(uint32_t addr, uint32_t* f) {
    asm volatile("ldmatrix.sync.aligned.m8n8.x4.trans.shared.b16 {%0,%1,%2,%3}, [%4];"
                 : "=r"(f[0]), "=r"(f[1]), "=r"(f[2]), "=r"(f[3]) : "r"(addr));
}
__device__ __forceinline__ void mma_bf16(float* d, const uint32_t* a, const uint32_t* b) {
    asm volatile("mma.sync.aligned.m16n8k16.row.col.f32.bf16.bf16.f32 "
                 "{%0,%1,%2,%3}, {%4,%5,%6,%7}, {%8,%9}, {%0,%1,%2,%3};"
                 : "+f"(d[0]), "+f"(d[1]), "+f"(d[2]), "+f"(d[3])
                 : "r"(a[0]), "r"(a[1]), "r"(a[2]), "r"(a[3]),
                   "r"(b[0]), "r"(b[1]));
}

// ---------------------------------------------------------------------------
// Kernel 1: fused gate + conversions in ONE launch.
// blocks [0,1250): gate (512 pairs each)
// blocks [1250, 1250+12800): conv A ; then 2048 W_K ; then 2048 W_Q
// ---------------------------------------------------------------------------
#define GATE_BLKS 1250
#define CONVA_BLKS 12800
#define CONVW_BLKS 2048
#define PRE_BLKS (GATE_BLKS + CONVA_BLKS + 2 * CONVW_BLKS)

__global__ __launch_bounds__(256, 4) void pre_kernel(
    const float* __restrict__ G, const float* __restrict__ Wg,
    const float* __restrict__ bg, float* __restrict__ gwout,
    const float* __restrict__ A, const float* __restrict__ WK,
    const float* __restrict__ WQ,
    __nv_bfloat16* __restrict__ Ah, __nv_bfloat16* __restrict__ Al,
    __nv_bfloat16* __restrict__ WKh, __nv_bfloat16* __restrict__ WKl,
    __nv_bfloat16* __restrict__ WQh, __nv_bfloat16* __restrict__ WQl)
{
    int bx = blockIdx.x;
    int tid = threadIdx.x;

    if (bx >= GATE_BLKS) {
        // -------- conversion part --------
        int cb = bx - GATE_BLKS;
        const float* X;
        __nv_bfloat16 *hi, *lo;
        int seg;
        if (cb < CONVA_BLKS)                 { X = A;  hi = Ah;  lo = Al;  seg = cb; }
        else if (cb < CONVA_BLKS + CONVW_BLKS){ X = WK; hi = WKh; lo = WKl; seg = cb - CONVA_BLKS; }
        else                                 { X = WQ; hi = WQh; lo = WQl; seg = cb - CONVA_BLKS - CONVW_BLKS; }

        size_t i = ((size_t)seg * 256 + tid) * 4;
        float4 v = *(const float4*)(X + i);
        float xs[4] = {v.x, v.y, v.z, v.w};
        __nv_bfloat16 h[4], l[4];
#pragma unroll
        for (int e = 0; e < 4; e++) {
            h[e] = __float2bfloat16(xs[e]);
            l[e] = __float2bfloat16(xs[e] - __bfloat162float(h[e]));
        }
        *(__nv_bfloat162*)(hi + i)     = __nv_bfloat162(h[0], h[1]);
        *(__nv_bfloat162*)(hi + i + 2) = __nv_bfloat162(h[2], h[3]);
        *(__nv_bfloat162*)(lo + i)     = __nv_bfloat162(l[0], l[1]);
        *(__nv_bfloat162*)(lo + i + 2) = __nv_bfloat162(l[2], l[3]);
        return;
    }

    // -------- gate part: 2 pairs per thread --------
    __shared__ float sW[64][16];
    __shared__ float sb[16];
    if (tid < 16) sb[tid] = bg[tid];
    for (int idx = tid; idx < 64 * 16; idx += 256)
        sW[idx >> 4][idx & 15] = Wg[idx];
    __syncthreads();

    int p0 = bx * 512 + tid;

    float acc0[16], acc1[16];
#pragma unroll
    for (int hh = 0; hh < 16; hh++) { acc0[hh] = sb[hh]; acc1[hh] = sb[hh]; }

    const float4* g4 = (const float4*)(G + (size_t)p0 * 64);

#pragma unroll 4
    for (int k4 = 0; k4 < 16; k4++) {
        float4 gv0 = g4[k4];
        float4 gv1 = g4[256 * 16 + k4];
        float a0[4] = {gv0.x, gv0.y, gv0.z, gv0.w};
        float a1[4] = {gv1.x, gv1.y, gv1.z, gv1.w};
#pragma unroll
        for (int e = 0; e < 4; e++) {
            int k = 4 * k4 + e;
            float ge0 = a0[e], ge1 = a1[e];
            float4 w0 = *(const float4*)&sW[k][0];
            acc0[0] += ge0 * w0.x; acc1[0] += ge1 * w0.x;
            acc0[1] += ge0 * w0.y; acc1[1] += ge1 * w0.y;
            acc0[2] += ge0 * w0.z; acc1[2] += ge1 * w0.z;
            acc0[3] += ge0 * w0.w; acc1[3] += ge1 * w0.w;
            float4 w1 = *(const float4*)&sW[k][4];
            acc0[4] += ge0 * w1.x; acc1[4] += ge1 * w1.x;
            acc0[5] += ge0 * w1.y; acc1[5] += ge1 * w1.y;
            acc0[6] += ge0 * w1.z; acc1[6] += ge1 * w1.z;
            acc0[7] += ge0 * w1.w; acc1[7] += ge1 * w1.w;
            float4 w2 = *(const float4*)&sW[k][8];
            acc0[8]  += ge0 * w2.x; acc1[8]  += ge1 * w2.x;
            acc0[9]  += ge0 * w2.y; acc1[9]  += ge1 * w2.y;
            acc0[10] += ge0 * w2.z; acc1[10] += ge1 * w2.z;
            acc0[11] += ge0 * w2.w; acc1[11] += ge1 * w2.w;
            float4 w3 = *(const float4*)&sW[k][12];
            acc0[12] += ge0 * w3.x; acc1[12] += ge1 * w3.x;
            acc0[13] += ge0 * w3.y; acc1[13] += ge1 * w3.y;
            acc0[14] += ge0 * w3.z; acc1[14] += ge1 * w3.z;
            acc0[15] += ge0 * w3.w; acc1[15] += ge1 * w3.w;
        }
    }

#pragma unroll
    for (int q = 0; q < 2; q++) {
        int p  = p0 + q * 256;
        int b  = p / (N_ * N_);
        int lp = p - b * (N_ * N_);
        float* ob = gwout + (size_t)b * (NR_ * N_ * N_) + lp;
        float* ac = q ? acc1 : acc0;
#pragma unroll
        for (int hh = 0; hh < 16; hh++)
            ob[(size_t)hh * (N_ * N_)] = fmaxf(ac[hh], 1e-6f);
    }
}

// ---------------------------------------------------------------------------
// Kernel 2: bf16 3-pass GEMM via mma.sync (unchanged from R8 win).
// CTA tile 256x128, 8 warps (4x2), warp tile 64x64, KC=64, 2-stage pipeline.
// ---------------------------------------------------------------------------
#define KC 64
#define NCHUNKS (D_ / KC)        // 32
#define STAGEBYTES 98304
#define GEMM_SMEM (2 * STAGEBYTES)

__global__ __launch_bounds__(256, 1) void gemm_mma(
    const __nv_bfloat16* __restrict__ Ah, const __nv_bfloat16* __restrict__ Al,
    const __nv_bfloat16* __restrict__ WKh, const __nv_bfloat16* __restrict__ WKl,
    const __nv_bfloat16* __restrict__ WQh, const __nv_bfloat16* __restrict__ WQl,
    const float* __restrict__ bK, const float* __restrict__ bQ,
    float* __restrict__ gK, float* __restrict__ gQ)
{
    extern __shared__ char smem[];
    uint32_t sbase = smem_u32(smem);
    int tid = threadIdx.x;
    int wid = tid >> 5, lane = tid & 31;
    int wm = wid >> 1, wn = wid & 1;

    const __nv_bfloat16 *Wh, *Wl;
    const float* bias;
    float* C;
    if (blockIdx.z == 0) { Wh = WKh; Wl = WKl; bias = bK; C = gK; }
    else                 { Wh = WQh; Wl = WQl; bias = bQ; C = gQ; }

    int m0 = blockIdx.y * 256;
    int n0 = blockIdx.x * 128;

    float acc[4][8][4];
#pragma unroll
    for (int mi = 0; mi < 4; mi++)
#pragma unroll
        for (int nj = 0; nj < 8; nj++)
#pragma unroll
            for (int e = 0; e < 4; e++) acc[mi][nj][e] = 0.f;

    auto load_chunk = [&](int c, int s) {
        int k0 = c * KC;
        uint32_t base = sbase + s * STAGEBYTES;
#pragma unroll
        for (int t = 0; t < 2; t++) {
            const __nv_bfloat16* src = t ? Al : Ah;
#pragma unroll
            for (int l2 = 0; l2 < 8; l2++) {
                int id = tid + l2 * 256;
                int r = id >> 3, cc = id & 7;
                cp_async16(base + t * 32768 + r * 128 + ((cc ^ (r & 7)) << 4),
                           src + (size_t)(m0 + r) * 2048 + k0 + cc * 8);
            }
        }
#pragma unroll
        for (int t = 0; t < 2; t++) {
            const __nv_bfloat16* src = t ? Wl : Wh;
#pragma unroll
            for (int l2 = 0; l2 < 4; l2++) {
                int id = tid + l2 * 256;
                int k = id >> 4, cc = id & 15;
                cp_async16(base + 65536 + t * 16384 + k * 256 + ((cc ^ (k & 7)) << 4),
                           src + (size_t)(k0 + k) * 1024 + n0 + cc * 8);
            }
        }
        CP_COMMIT();
    };

    load_chunk(0, 0);
    load_chunk(1, 1);

    int ar  = lane & 15;
    int acs = lane >> 4;
    int wg8 = lane >> 3;
    int wk8 = lane & 7;
    int wks = (wg8 & 1) * 8;
    int wns = wg8 >> 1;

    for (int c = 0; c < NCHUNKS; c++) {
        CP_WAIT(1);
        __syncthreads();
        uint32_t base = sbase + (c & 1) * STAGEBYTES;

#pragma unroll
        for (int ki = 0; ki < 4; ki++) {
            uint32_t afh[4][4], afl[4][4];
#pragma unroll
            for (int mi = 0; mi < 4; mi++) {
                int r = wm * 64 + mi * 16 + ar;
                int cc = 2 * ki + acs;
                uint32_t off = (uint32_t)(r * 128 + ((cc ^ (r & 7)) << 4));
                ldsm_x4(base + off, afh[mi]);
                ldsm_x4(base + 32768 + off, afl[mi]);
            }
#pragma unroll
            for (int np = 0; np < 4; np++) {
                int k  = ki * 16 + wks + wk8;
                int cc = wn * 8 + 2 * np + wns;
                uint32_t off = (uint32_t)(k * 256 + ((cc ^ (k & 7)) << 4));
                uint32_t qh[4], ql[4];
                ldsm_x4t(base + 65536 + off, qh);
                ldsm_x4t(base + 81920 + off, ql);
                uint32_t bh0[2] = {qh[0], qh[1]}, bh1[2] = {qh[2], qh[3]};
                uint32_t bl0[2] = {ql[0], ql[1]}, bl1[2] = {ql[2], ql[3]};
#pragma unroll
                for (int mi = 0; mi < 4; mi++) {
                    mma_bf16(acc[mi][2 * np],     afh[mi], bh0);
                    mma_bf16(acc[mi][2 * np],     afh[mi], bl0);
                    mma_bf16(acc[mi][2 * np],     afl[mi], bh0);
                    mma_bf16(acc[mi][2 * np + 1], afh[mi], bh1);
                    mma_bf16(acc[mi][2 * np + 1], afh[mi], bl1);
                    mma_bf16(acc[mi][2 * np + 1], afl[mi], bh1);
                }
            }
        }
        __syncthreads();
        if (c + 2 < NCHUNKS) load_chunk(c + 2, c & 1); else CP_COMMIT();
    }

    int g = lane >> 2, t4 = lane & 3;
    float bcol[8][2];
#pragma unroll
    for (int nj = 0; nj < 8; nj++) {
        int col = n0 + wn * 64 + nj * 8 + t4 * 2;
        bcol[nj][0] = __ldg(bias + col);
        bcol[nj][1] = __ldg(bias + col + 1);
    }
#pragma unroll
    for (int mi = 0; mi < 4; mi++) {
#pragma unroll
        for (int half = 0; half < 2; half++) {
            int m = m0 + wm * 64 + mi * 16 + g + half * 8;
            float* crow = C + (size_t)m * 1024 + n0 + wn * 64;
#pragma unroll
            for (int nj = 0; nj < 8; nj++) {
                int col = nj * 8 + t4 * 2;
                float2 v;
                v.x = acc[mi][nj][half * 2 + 0] + bcol[nj][0];
                v.y = acc[mi][nj][half * 2 + 1] + bcol[nj][1];
                *(float2*)(crow + col) = v;
            }
        }
    }
}

// ---------------------------------------------------------------------------
// Kernel 3: attention logits per (b,h).  e = gw * exp(K.Q/8), written IN PLACE
// over g_gwT.  smem: K,Q tiles only (58.2KB) -> 3 CTAs/SM.
// ---------------------------------------------------------------------------
#define KQPAD 65

__global__ __launch_bounds__(256, 3) void attn_logits_kernel(
    const float* __restrict__ Kmat, const float* __restrict__ Qmat,
    float* __restrict__ gw)
{
    extern __shared__ float sm[];
    float* Ks = sm;                    // 112 x 65
    float* Qs = sm + 112 * KQPAD;      // 112 x 65

    int h = blockIdx.x;
    int b = blockIdx.y;
    int tid = threadIdx.x;
    int tx = tid & 15, ty = tid >> 4;

    for (int idx = tid; idx < 112 * 64; idx += 256) {
        int i = idx >> 6, d = idx & 63;
        float kv = 0.f, qv = 0.f;
        if (i < 100) {
            size_t gofs = (size_t)(b * 100 + i) * 1024 + h * 64 + d;
            kv = Kmat[gofs];
            qv = Qmat[gofs];
        }
        Ks[i * KQPAD + d] = kv;
        Qs[i * KQPAD + d] = qv;
    }
    __syncthreads();

    float acc[7][7];
#pragma unroll
    for (int ii = 0; ii < 7; ii++)
#pragma unroll
        for (int jj = 0; jj < 7; jj++) acc[ii][jj] = 0.f;

    for (int d = 0; d < 64; d++) {
        float kk[7], qq[7];
#pragma unroll
        for (int ii = 0; ii < 7; ii++) kk[ii] = Ks[(ty + 16 * ii) * KQPAD + d];
#pragma unroll
        for (int jj = 0; jj < 7; jj++) qq[jj] = Qs[(tx + 16 * jj) * KQPAD + d];
#pragma unroll
        for (int ii = 0; ii < 7; ii++)
#pragma unroll
            for (int jj = 0; jj < 7; jj++)
                acc[ii][jj] += kk[ii] * qq[jj];
    }

    float* gwb = gw + ((size_t)(b * 16 + h)) * 10000;
#pragma unroll
    for (int ii = 0; ii < 7; ii++) {
        int i = ty + 16 * ii;
        if (i >= 100) continue;
#pragma unroll
        for (int jj = 0; jj < 7; jj++) {
            int j = tx + 16 * jj;
            if (j >= 100) continue;
            float* ep = gwb + i * 100 + j;
            *ep = *ep * __expf(acc[ii][jj] * 0.125f);
        }
    }
}

// ---------------------------------------------------------------------------
// Kernel 4: AV per (b,h).  out[j,d] = (sum_i e[i,j] V[i,d]) / (sum_i e[i,j])
//            * ws + bs.
// V (100x128 f32, 51.2KB) via cp.async; e streamed in 4 chunks of 25 rows,
// double-buffered (2 x 11.2KB).  smem total ~74KB -> 3 CTAs/SM.
// ---------------------------------------------------------------------------
#define AVPAD 112
#define AV_FIN0 12800                     // float index of fin buffers
#define AV_CS   (AV_FIN0 + 2 * 25 * AVPAD)  // 18400
#define AV_SMEM ((AV_CS + 112) * 4)       // 74048 bytes

__global__ __launch_bounds__(256, 3) void attn_av_kernel(
    const float* __restrict__ e_g, const float* __restrict__ A,
    const float* __restrict__ wsp, const float* __restrict__ bsp,
    float* __restrict__ out)
{
    extern __shared__ float sm[];
    uint32_t sbase = smem_u32(sm);

    int h = blockIdx.x;
    int b = blockIdx.y;
    int tid = threadIdx.x;
    int tx = tid & 15, ty = tid >> 4;

    const float* eb = e_g + ((size_t)(b * 16 + h)) * 10000;

    // prefetch V (100 x 128 f32 = 3200 x 16B) + e chunk 0 -> group 0
    for (int idx = tid; idx < 3200; idx += 256) {
        int i = idx >> 5, cc = idx & 31;
        cp_async16(sbase + (uint32_t)(i * 512 + cc * 16),
                   A + (size_t)(b * 100 + i) * 2048 + h * 128 + cc * 4);
    }
    // e chunk loader: chunk c = rows [25c, 25c+25), 25 rows x 25 x 16B
    auto load_echunk = [&](int c) {
        uint32_t dst0 = sbase + (uint32_t)((AV_FIN0 + (c & 1) * 25 * AVPAD) * 4);
        for (int idx = tid; idx < 625; idx += 256) {
            int r = idx / 25, cc = idx - r * 25;
            cp_async16(dst0 + (uint32_t)(r * AVPAD * 4 + cc * 16),
                       eb + (25 * c + r) * 100 + cc * 4);
        }
        CP_COMMIT();
    };
    load_echunk(0);   // group 0 (V + chunk 0)
    load_echunk(1);   // group 1

    float r[7][8];
#pragma unroll
    for (int jj = 0; jj < 7; jj++)
#pragma unroll
        for (int dd = 0; dd < 8; dd++) r[jj][dd] = 0.f;
    float cacc = 0.f;

    for (int c = 0; c < 4; c++) {
        if (c < 3) { CP_WAIT(1); } else { CP_WAIT(0); }
        __syncthreads();
        const float* fb = sm + AV_FIN0 + (c & 1) * 25 * AVPAD;

        // column sums (threads 0..99, one column each)
        if (tid < 100) {
#pragma unroll 5
            for (int ii = 0; ii < 25; ii++) cacc += fb[ii * AVPAD + tid];
        }

        // AV accumulation
        for (int ii = 0; ii < 25; ii++) {
            int i = 25 * c + ii;
            float vv[8], ff[7];
#pragma unroll
            for (int dd = 0; dd < 8; dd++) vv[dd] = sm[i * 128 + tx + 16 * dd];
#pragma unroll
            for (int jj = 0; jj < 7; jj++) ff[jj] = fb[ii * AVPAD + ty + 16 * jj];
#pragma unroll
            for (int jj = 0; jj < 7; jj++)
#pragma unroll
                for (int dd = 0; dd < 8; dd++)
                    r[jj][dd] += vv[dd] * ff[jj];
        }
        __syncthreads();
        if (c + 2 < 4) load_echunk(c + 2);
    }

    if (tid < 100) sm[AV_CS + tid] = cacc;
    __syncthreads();

    float ws = wsp[0], bs = bsp[0];
#pragma unroll
    for (int jj = 0; jj < 7; jj++) {
        int j = ty + 16 * jj;
        if (j >= 100) continue;
        float rc = (1.f / sm[AV_CS + j]) * ws;
        float* orow = out + (size_t)(b * 100 + j) * 2048 + h * 128;
#pragma unroll
        for (int dd = 0; dd < 8; dd++) {
            int d = tx + 16 * dd;
            orow[d] = (r[jj][dd] * rc) + bs;
        }
    }
}

// ---------------------------------------------------------------------------
// Launcher
// ---------------------------------------------------------------------------
extern "C" void kernel_launch(void* const* d_in, const int* in_sizes, int n_in,
                              void* d_out, int out_size)
{
    const float* a_feat = (const float*)d_in[0];
    const float* g_feat = (const float*)d_in[1];
    const float* W_g    = (const float*)d_in[4];
    const float* b_g    = (const float*)d_in[5];
    const float* W_K    = (const float*)d_in[6];
    const float* b_K    = (const float*)d_in[7];
    const float* W_Q    = (const float*)d_in[8];
    const float* b_Q    = (const float*)d_in[9];
    const float* w_s    = (const float*)d_in[10];
    const float* b_s    = (const float*)d_in[11];
    float* out          = (float*)d_out;

    float *Kp, *Qp, *gwp;
    __nv_bfloat16 *Ahp, *Alp, *WKhp, *WKlp, *WQhp, *WQlp;
    cudaGetSymbolAddress((void**)&Kp,  g_K);
    cudaGetSymbolAddress((void**)&Qp,  g_Q);
    cudaGetSymbolAddress((void**)&gwp, g_gwT);
    cudaGetSymbolAddress((void**)&Ahp, g_Ahi);
    cudaGetSymbolAddress((void**)&Alp, g_Alo);
    cudaGetSymbolAddress((void**)&WKhp, g_WKhi);
    cudaGetSymbolAddress((void**)&WKlp, g_WKlo);
    cudaGetSymbolAddress((void**)&WQhp, g_WQhi);
    cudaGetSymbolAddress((void**)&WQlp, g_WQlo);

    // 1) fused gate + conversions
    pre_kernel<<<PRE_BLKS, 256>>>(g_feat, W_g, b_g, gwp,
                                  a_feat, W_K, W_Q,
                                  Ahp, Alp, WKhp, WKlp, WQhp, WQlp);

    // 2) K & Q GEMMs (mma.sync bf16 3-pass, 256x128 CTA tile, 64x64 warp tile)
    cudaFuncSetAttribute(gemm_mma, cudaFuncAttributeMaxDynamicSharedMemorySize,
                         GEMM_SMEM);
    dim3 ggrid(KQ_COLS / 128, P_ / 256, 2);   // (8, 25, 2)
    gemm_mma<<<ggrid, 256, GEMM_SMEM>>>(Ahp, Alp, WKhp, WKlp, WQhp, WQlp,
                                        b_K, b_Q, Kp, Qp);

    // 3) logits (e overwrites gw in place)
    int lsmem = 2 * 112 * KQPAD * (int)sizeof(float);
    cudaFuncSetAttribute(attn_logits_kernel,
                         cudaFuncAttributeMaxDynamicSharedMemorySize, lsmem);
    dim3 agrid(NR_, B_);
    attn_logits_kernel<<<agrid, 256, lsmem>>>(Kp, Qp, gwp);

    // 4) AV + normalize + affine
    cudaFuncSetAttribute(attn_av_kernel,
                         cudaFuncAttributeMaxDynamicSharedMemorySize, AV_SMEM);
    attn_av_kernel<<<agrid, 256, AV_SMEM>>>(gwp, a_feat, w_s, b_s, out);
}

// round 12
// speedup vs baseline: 1.1614x; 1.0049x over previous
#include <cuda_runtime.h>
#include <cuda_bf16.h>
#include <cstdint>

// Problem constants
#define B_   64
#define N_   100
#define D_   2048
#define NR_  16
#define DK_  64
#define DV_  128
#define P_   (B_*N_)          // 6400
#define KQ_COLS (NR_*DK_)     // 1024
#define PAIRS (B_*N_*N_)      // 640000

// ---------------------------------------------------------------------------
// Scratch (device globals; allocation APIs are forbidden)
// ---------------------------------------------------------------------------
__device__ float g_K[P_ * KQ_COLS];          // 6400 x 1024
__device__ float g_Q[P_ * KQ_COLS];          // 6400 x 1024
__device__ float g_gwT[B_ * NR_ * N_ * N_];  // [b][h][i*100+j]; e overwrites gw

__device__ __align__(16) __nv_bfloat16 g_Ahi[P_ * D_];        // [m][k]
__device__ __align__(16) __nv_bfloat16 g_Alo[P_ * D_];
__device__ __align__(16) __nv_bfloat16 g_WKhi[D_ * KQ_COLS];  // [k][n]
__device__ __align__(16) __nv_bfloat16 g_WKlo[D_ * KQ_COLS];
__device__ __align__(16) __nv_bfloat16 g_WQhi[D_ * KQ_COLS];
__device__ __align__(16) __nv_bfloat16 g_WQlo[D_ * KQ_COLS];

// ---------------------------------------------------------------------------
// PTX helpers
// ---------------------------------------------------------------------------
__device__ __forceinline__ uint32_t smem_u32(const void* p) {
    uint32_t a;
    asm("{ .reg .u64 t; cvta.to.shared.u64 t, %1; cvt.u32.u64 %0, t; }"
        : "=r"(a) : "l"(p));
    return a;
}
__device__ __forceinline__ void cp_async16(uint32_t dst, const void* src) {
    asm volatile("cp.async.cg.shared.global [%0], [%1], 16;" :: "r"(dst), "l"(src));
}
#define CP_COMMIT() asm volatile("cp.async.commit_group;" ::: "memory")
#define CP_WAIT(n)  asm volatile("cp.async.wait_group %0;" :: "n"(n) : "memory")

__device__ __forceinline__ void ldsm_x4(uint32_t addr, uint32_t* f) {
    asm volatile("ldmatrix.sync.aligned.m8n8.x4.shared.b16 {%0,%1,%2,%3}, [%4];"
                 : "=r"(f[0]), "=r"(f[1]), "=r"(f[2]), "=r"(f[3]) : "r"(addr));
}
__device__ __forceinline__ void ldsm_x4t(uint32_t addr, uint32_t* f) {
    asm volatile("ldmatrix.sync.aligned.m8n8.x4.trans.shared.b16 {%0,%1,%2,%3}, [%4];"
                 : "=r"(f[0]), "=r"(f[1]), "=r"(f[2]), "=r"(f[3]) : "r"(addr));
}
__device__ __forceinline__ void mma_bf16(float* d, const uint32_t* a, const uint32_t* b) {
    asm volatile("mma.sync.aligned.m16n8k16.row.col.f32.bf16.bf16.f32 "
                 "{%0,%1,%2,%3}, {%4,%5,%6,%7}, {%8,%9}, {%0,%1,%2,%3};"
                 : "+f"(d[0]), "+f"(d[1]), "+f"(d[2]), "+f"(d[3])
                 : "r"(a[0]), "r"(a[1]), "r"(a[2]), "r"(a[3]),
                   "r"(b[0]), "r"(b[1]));
}

// ---------------------------------------------------------------------------
// Kernel 1: fused gate + conversions (unchanged from R9 win).
// ---------------------------------------------------------------------------
#define GATE_BLKS 1250
#define CONVA_BLKS 12800
#define CONVW_BLKS 2048
#define PRE_BLKS (GATE_BLKS + CONVA_BLKS + 2 * CONVW_BLKS)

__global__ __launch_bounds__(256, 4) void pre_kernel(
    const float* __restrict__ G, const float* __restrict__ Wg,
    const float* __restrict__ bg, float* __restrict__ gwout,
    const float* __restrict__ A, const float* __restrict__ WK,
    const float* __restrict__ WQ,
    __nv_bfloat16* __restrict__ Ah, __nv_bfloat16* __restrict__ Al,
    __nv_bfloat16* __restrict__ WKh, __nv_bfloat16* __restrict__ WKl,
    __nv_bfloat16* __restrict__ WQh, __nv_bfloat16* __restrict__ WQl)
{
    int bx = blockIdx.x;
    int tid = threadIdx.x;

    if (bx >= GATE_BLKS) {
        int cb = bx - GATE_BLKS;
        const float* X;
        __nv_bfloat16 *hi, *lo;
        int seg;
        if (cb < CONVA_BLKS)                  { X = A;  hi = Ah;  lo = Al;  seg = cb; }
        else if (cb < CONVA_BLKS + CONVW_BLKS){ X = WK; hi = WKh; lo = WKl; seg = cb - CONVA_BLKS; }
        else                                  { X = WQ; hi = WQh; lo = WQl; seg = cb - CONVA_BLKS - CONVW_BLKS; }

        size_t i = ((size_t)seg * 256 + tid) * 4;
        float4 v = *(const float4*)(X + i);
        float xs[4] = {v.x, v.y, v.z, v.w};
        __nv_bfloat16 h[4], l[4];
#pragma unroll
        for (int e = 0; e < 4; e++) {
            h[e] = __float2bfloat16(xs[e]);
            l[e] = __float2bfloat16(xs[e] - __bfloat162float(h[e]));
        }
        *(__nv_bfloat162*)(hi + i)     = __nv_bfloat162(h[0], h[1]);
        *(__nv_bfloat162*)(hi + i + 2) = __nv_bfloat162(h[2], h[3]);
        *(__nv_bfloat162*)(lo + i)     = __nv_bfloat162(l[0], l[1]);
        *(__nv_bfloat162*)(lo + i + 2) = __nv_bfloat162(l[2], l[3]);
        return;
    }

    __shared__ float sW[64][16];
    __shared__ float sb[16];
    if (tid < 16) sb[tid] = bg[tid];
    for (int idx = tid; idx < 64 * 16; idx += 256)
        sW[idx >> 4][idx & 15] = Wg[idx];
    __syncthreads();

    int p0 = bx * 512 + tid;

    float acc0[16], acc1[16];
#pragma unroll
    for (int hh = 0; hh < 16; hh++) { acc0[hh] = sb[hh]; acc1[hh] = sb[hh]; }

    const float4* g4 = (const float4*)(G + (size_t)p0 * 64);

#pragma unroll 4
    for (int k4 = 0; k4 < 16; k4++) {
        float4 gv0 = g4[k4];
        float4 gv1 = g4[256 * 16 + k4];
        float a0[4] = {gv0.x, gv0.y, gv0.z, gv0.w};
        float a1[4] = {gv1.x, gv1.y, gv1.z, gv1.w};
#pragma unroll
        for (int e = 0; e < 4; e++) {
            int k = 4 * k4 + e;
            float ge0 = a0[e], ge1 = a1[e];
            float4 w0 = *(const float4*)&sW[k][0];
            acc0[0] += ge0 * w0.x; acc1[0] += ge1 * w0.x;
            acc0[1] += ge0 * w0.y; acc1[1] += ge1 * w0.y;
            acc0[2] += ge0 * w0.z; acc1[2] += ge1 * w0.z;
            acc0[3] += ge0 * w0.w; acc1[3] += ge1 * w0.w;
            float4 w1 = *(const float4*)&sW[k][4];
            acc0[4] += ge0 * w1.x; acc1[4] += ge1 * w1.x;
            acc0[5] += ge0 * w1.y; acc1[5] += ge1 * w1.y;
            acc0[6] += ge0 * w1.z; acc1[6] += ge1 * w1.z;
            acc0[7] += ge0 * w1.w; acc1[7] += ge1 * w1.w;
            float4 w2 = *(const float4*)&sW[k][8];
            acc0[8]  += ge0 * w2.x; acc1[8]  += ge1 * w2.x;
            acc0[9]  += ge0 * w2.y; acc1[9]  += ge1 * w2.y;
            acc0[10] += ge0 * w2.z; acc1[10] += ge1 * w2.z;
            acc0[11] += ge0 * w2.w; acc1[11] += ge1 * w2.w;
            float4 w3 = *(const float4*)&sW[k][12];
            acc0[12] += ge0 * w3.x; acc1[12] += ge1 * w3.x;
            acc0[13] += ge0 * w3.y; acc1[13] += ge1 * w3.y;
            acc0[14] += ge0 * w3.z; acc1[14] += ge1 * w3.z;
            acc0[15] += ge0 * w3.w; acc1[15] += ge1 * w3.w;
        }
    }

#pragma unroll
    for (int q = 0; q < 2; q++) {
        int p  = p0 + q * 256;
        int b  = p / (N_ * N_);
        int lp = p - b * (N_ * N_);
        float* ob = gwout + (size_t)b * (NR_ * N_ * N_) + lp;
        float* ac = q ? acc1 : acc0;
#pragma unroll
        for (int hh = 0; hh < 16; hh++)
            ob[(size_t)hh * (N_ * N_)] = fmaxf(ac[hh], 1e-6f);
    }
}

// ---------------------------------------------------------------------------
// Kernel 2: bf16 3-pass GEMM via mma.sync.
// CTA tile 128x128, 4 warps (2x2), warp tile 64x64, KC=32, 3-stage pipeline,
// 96KB smem -> 2 CTAs/SM.  grid (8, 50, 2): z=0->K, z=1->Q.
//
// stage layout (32KB): Ahi[128][32] @0 (8KB), Alo @8192,
//                      Whi[32][128] @16384 (8KB), Wlo @24576.
// A swizzle (64B rows): off = r*64 + ((cc ^ (r&3))<<4), cc = 16B chunk 0..3.
// W swizzle (256B rows): off = k*256 + ((cc ^ (k&7))<<4), cc = 16B chunk 0..15.
// ---------------------------------------------------------------------------
#define KC 32
#define NCHUNKS (D_ / KC)        // 64
#define STAGEBYTES 32768
#define GEMM_SMEM (3 * STAGEBYTES)

__global__ __launch_bounds__(128, 2) void gemm_mma(
    const __nv_bfloat16* __restrict__ Ah, const __nv_bfloat16* __restrict__ Al,
    const __nv_bfloat16* __restrict__ WKh, const __nv_bfloat16* __restrict__ WKl,
    const __nv_bfloat16* __restrict__ WQh, const __nv_bfloat16* __restrict__ WQl,
    const float* __restrict__ bK, const float* __restrict__ bQ,
    float* __restrict__ gK, float* __restrict__ gQ)
{
    extern __shared__ char smem[];
    uint32_t sbase = smem_u32(smem);
    int tid = threadIdx.x;
    int wid = tid >> 5, lane = tid & 31;
    int wm = wid >> 1, wn = wid & 1;   // 2 x 2 warp grid, warp tile 64x64

    const __nv_bfloat16 *Wh, *Wl;
    const float* bias;
    float* C;
    if (blockIdx.z == 0) { Wh = WKh; Wl = WKl; bias = bK; C = gK; }
    else                 { Wh = WQh; Wl = WQl; bias = bQ; C = gQ; }

    int m0 = blockIdx.y * 128;
    int n0 = blockIdx.x * 128;

    float acc[4][8][4];
#pragma unroll
    for (int mi = 0; mi < 4; mi++)
#pragma unroll
        for (int nj = 0; nj < 8; nj++)
#pragma unroll
            for (int e = 0; e < 4; e++) acc[mi][nj][e] = 0.f;

    // ---- async load of one K-chunk into stage s ----
    auto load_chunk = [&](int c, int s) {
        int k0 = c * KC;
        uint32_t base = sbase + s * STAGEBYTES;
        // A hi/lo: 128 rows x 32 k = 64B rows, 512 chunks of 16B each
#pragma unroll
        for (int t = 0; t < 2; t++) {
            const __nv_bfloat16* src = t ? Al : Ah;
#pragma unroll
            for (int l2 = 0; l2 < 4; l2++) {
                int id = tid + l2 * 128;        // 0..511
                int r = id >> 2, cc = id & 3;
                cp_async16(base + t * 8192 + r * 64 + ((cc ^ (r & 3)) << 4),
                           src + (size_t)(m0 + r) * 2048 + k0 + cc * 8);
            }
        }
        // W hi/lo: 32 k-rows x 128 n = 256B rows, 512 chunks
#pragma unroll
        for (int t = 0; t < 2; t++) {
            const __nv_bfloat16* src = t ? Wl : Wh;
#pragma unroll
            for (int l2 = 0; l2 < 4; l2++) {
                int id = tid + l2 * 128;
                int k = id >> 4, cc = id & 15;
                cp_async16(base + 16384 + t * 8192 + k * 256 + ((cc ^ (k & 7)) << 4),
                           src + (size_t)(k0 + k) * 1024 + n0 + cc * 8);
            }
        }
        CP_COMMIT();
    };

    load_chunk(0, 0);
    load_chunk(1, 1);
    load_chunk(2, 2);

    // ldmatrix lane address components
    int ar  = lane & 15;          // A: row within 16-row block
    int acs = lane >> 4;          // A: k16-half select
    int wg8 = lane >> 3;          // W: 8-lane group 0..3
    int wk8 = lane & 7;
    int wks = (wg8 & 1) * 8;
    int wns = wg8 >> 1;

    int s = 0;
    for (int c = 0; c < NCHUNKS; c++) {
        CP_WAIT(2);
        __syncthreads();
        uint32_t base = sbase + s * STAGEBYTES;

#pragma unroll
        for (int ki = 0; ki < 2; ki++) {
            uint32_t afh[4][4], afl[4][4];
#pragma unroll
            for (int mi = 0; mi < 4; mi++) {
                int r = wm * 64 + mi * 16 + ar;
                int cc = 2 * ki + acs;
                uint32_t off = (uint32_t)(r * 64 + ((cc ^ (r & 3)) << 4));
                ldsm_x4(base + off, afh[mi]);
                ldsm_x4(base + 8192 + off, afl[mi]);
            }
#pragma unroll
            for (int np = 0; np < 4; np++) {
                int k  = ki * 16 + wks + wk8;
                int cc = wn * 8 + 2 * np + wns;
                uint32_t off = (uint32_t)(k * 256 + ((cc ^ (k & 7)) << 4));
                uint32_t qh[4], ql[4];
                ldsm_x4t(base + 16384 + off, qh);
                ldsm_x4t(base + 24576 + off, ql);
                uint32_t bh0[2] = {qh[0], qh[1]}, bh1[2] = {qh[2], qh[3]};
                uint32_t bl0[2] = {ql[0], ql[1]}, bl1[2] = {ql[2], ql[3]};
#pragma unroll
                for (int mi = 0; mi < 4; mi++) {
                    mma_bf16(acc[mi][2 * np],     afh[mi], bh0);
                    mma_bf16(acc[mi][2 * np],     afh[mi], bl0);
                    mma_bf16(acc[mi][2 * np],     afl[mi], bh0);
                    mma_bf16(acc[mi][2 * np + 1], afh[mi], bh1);
                    mma_bf16(acc[mi][2 * np + 1], afh[mi], bl1);
                    mma_bf16(acc[mi][2 * np + 1], afl[mi], bh1);
                }
            }
        }
        __syncthreads();
        if (c + 3 < NCHUNKS) load_chunk(c + 3, s); else CP_COMMIT();
        s = (s == 2) ? 0 : s + 1;
    }

    // ---- epilogue: add bias, store fp32 ----
    int g = lane >> 2, t4 = lane & 3;
    float bcol[8][2];
#pragma unroll
    for (int nj = 0; nj < 8; nj++) {
        int col = n0 + wn * 64 + nj * 8 + t4 * 2;
        bcol[nj][0] = __ldg(bias + col);
        bcol[nj][1] = __ldg(bias + col + 1);
    }
#pragma unroll
    for (int mi = 0; mi < 4; mi++) {
#pragma unroll
        for (int half = 0; half < 2; half++) {
            int m = m0 + wm * 64 + mi * 16 + g + half * 8;
            float* crow = C + (size_t)m * 1024 + n0 + wn * 64;
#pragma unroll
            for (int nj = 0; nj < 8; nj++) {
                int col = nj * 8 + t4 * 2;
                float2 v;
                v.x = acc[mi][nj][half * 2 + 0] + bcol[nj][0];
                v.y = acc[mi][nj][half * 2 + 1] + bcol[nj][1];
                *(float2*)(crow + col) = v;
            }
        }
    }
}

// ---------------------------------------------------------------------------
// Kernel 3: attention logits per (b,h), in-place e over g_gwT (unchanged).
// ---------------------------------------------------------------------------
#define KQPAD 65

__global__ __launch_bounds__(256, 3) void attn_logits_kernel(
    const float* __restrict__ Kmat, const float* __restrict__ Qmat,
    float* __restrict__ gw)
{
    extern __shared__ float sm[];
    float* Ks = sm;
    float* Qs = sm + 112 * KQPAD;

    int h = blockIdx.x;
    int b = blockIdx.y;
    int tid = threadIdx.x;
    int tx = tid & 15, ty = tid >> 4;

    for (int idx = tid; idx < 112 * 64; idx += 256) {
        int i = idx >> 6, d = idx & 63;
        float kv = 0.f, qv = 0.f;
        if (i < 100) {
            size_t gofs = (size_t)(b * 100 + i) * 1024 + h * 64 + d;
            kv = Kmat[gofs];
            qv = Qmat[gofs];
        }
        Ks[i * KQPAD + d] = kv;
        Qs[i * KQPAD + d] = qv;
    }
    __syncthreads();

    float acc[7][7];
#pragma unroll
    for (int ii = 0; ii < 7; ii++)
#pragma unroll
        for (int jj = 0; jj < 7; jj++) acc[ii][jj] = 0.f;

    for (int d = 0; d < 64; d++) {
        float kk[7], qq[7];
#pragma unroll
        for (int ii = 0; ii < 7; ii++) kk[ii] = Ks[(ty + 16 * ii) * KQPAD + d];
#pragma unroll
        for (int jj = 0; jj < 7; jj++) qq[jj] = Qs[(tx + 16 * jj) * KQPAD + d];
#pragma unroll
        for (int ii = 0; ii < 7; ii++)
#pragma unroll
            for (int jj = 0; jj < 7; jj++)
                acc[ii][jj] += kk[ii] * qq[jj];
    }

    float* gwb = gw + ((size_t)(b * 16 + h)) * 10000;
#pragma unroll
    for (int ii = 0; ii < 7; ii++) {
        int i = ty + 16 * ii;
        if (i >= 100) continue;
#pragma unroll
        for (int jj = 0; jj < 7; jj++) {
            int j = tx + 16 * jj;
            if (j >= 100) continue;
            float* ep = gwb + i * 100 + j;
            *ep = *ep * __expf(acc[ii][jj] * 0.125f);
        }
    }
}

// ---------------------------------------------------------------------------
// Kernel 4: AV per (b,h) (unchanged from R9 win).
// ---------------------------------------------------------------------------
#define AVPAD 112
#define AV_FIN0 12800
#define AV_CS   (AV_FIN0 + 2 * 25 * AVPAD)
#define AV_SMEM ((AV_CS + 112) * 4)

__global__ __launch_bounds__(256, 3) void attn_av_kernel(
    const float* __restrict__ e_g, const float* __restrict__ A,
    const float* __restrict__ wsp, const float* __restrict__ bsp,
    float* __restrict__ out)
{
    extern __shared__ float sm[];
    uint32_t sbase = smem_u32(sm);

    int h = blockIdx.x;
    int b = blockIdx.y;
    int tid = threadIdx.x;
    int tx = tid & 15, ty = tid >> 4;

    const float* eb = e_g + ((size_t)(b * 16 + h)) * 10000;

    for (int idx = tid; idx < 3200; idx += 256) {
        int i = idx >> 5, cc = idx & 31;
        cp_async16(sbase + (uint32_t)(i * 512 + cc * 16),
                   A + (size_t)(b * 100 + i) * 2048 + h * 128 + cc * 4);
    }
    auto load_echunk = [&](int c) {
        uint32_t dst0 = sbase + (uint32_t)((AV_FIN0 + (c & 1) * 25 * AVPAD) * 4);
        for (int idx = tid; idx < 625; idx += 256) {
            int r = idx / 25, cc = idx - r * 25;
            cp_async16(dst0 + (uint32_t)(r * AVPAD * 4 + cc * 16),
                       eb + (25 * c + r) * 100 + cc * 4);
        }
        CP_COMMIT();
    };
    load_echunk(0);
    load_echunk(1);

    float r[7][8];
#pragma unroll
    for (int jj = 0; jj < 7; jj++)
#pragma unroll
        for (int dd = 0; dd < 8; dd++) r[jj][dd] = 0.f;
    float cacc = 0.f;

    for (int c = 0; c < 4; c++) {
        if (c < 3) { CP_WAIT(1); } else { CP_WAIT(0); }
        __syncthreads();
        const float* fb = sm + AV_FIN0 + (c & 1) * 25 * AVPAD;

        if (tid < 100) {
#pragma unroll 5
            for (int ii = 0; ii < 25; ii++) cacc += fb[ii * AVPAD + tid];
        }

        for (int ii = 0; ii < 25; ii++) {
            int i = 25 * c + ii;
            float vv[8], ff[7];
#pragma unroll
            for (int dd = 0; dd < 8; dd++) vv[dd] = sm[i * 128 + tx + 16 * dd];
#pragma unroll
            for (int jj = 0; jj < 7; jj++) ff[jj] = fb[ii * AVPAD + ty + 16 * jj];
#pragma unroll
            for (int jj = 0; jj < 7; jj++)
#pragma unroll
                for (int dd = 0; dd < 8; dd++)
                    r[jj][dd] += vv[dd] * ff[jj];
        }
        __syncthreads();
        if (c + 2 < 4) load_echunk(c + 2);
    }

    if (tid < 100) sm[AV_CS + tid] = cacc;
    __syncthreads();

    float ws = wsp[0], bs = bsp[0];
#pragma unroll
    for (int jj = 0; jj < 7; jj++) {
        int j = ty + 16 * jj;
        if (j >= 100) continue;
        float rc = (1.f / sm[AV_CS + j]) * ws;
        float* orow = out + (size_t)(b * 100 + j) * 2048 + h * 128;
#pragma unroll
        for (int dd = 0; dd < 8; dd++) {
            int d = tx + 16 * dd;
            orow[d] = (r[jj][dd] * rc) + bs;
        }
    }
}

// ---------------------------------------------------------------------------
// Launcher
// ---------------------------------------------------------------------------
extern "C" void kernel_launch(void* const* d_in, const int* in_sizes, int n_in,
                              void* d_out, int out_size)
{
    const float* a_feat = (const float*)d_in[0];
    const float* g_feat = (const float*)d_in[1];
    const float* W_g    = (const float*)d_in[4];
    const float* b_g    = (const float*)d_in[5];
    const float* W_K    = (const float*)d_in[6];
    const float* b_K    = (const float*)d_in[7];
    const float* W_Q    = (const float*)d_in[8];
    const float* b_Q    = (const float*)d_in[9];
    const float* w_s    = (const float*)d_in[10];
    const float* b_s    = (const float*)d_in[11];
    float* out          = (float*)d_out;

    float *Kp, *Qp, *gwp;
    __nv_bfloat16 *Ahp, *Alp, *WKhp, *WKlp, *WQhp, *WQlp;
    cudaGetSymbolAddress((void**)&Kp,  g_K);
    cudaGetSymbolAddress((void**)&Qp,  g_Q);
    cudaGetSymbolAddress((void**)&gwp, g_gwT);
    cudaGetSymbolAddress((void**)&Ahp, g_Ahi);
    cudaGetSymbolAddress((void**)&Alp, g_Alo);
    cudaGetSymbolAddress((void**)&WKhp, g_WKhi);
    cudaGetSymbolAddress((void**)&WKlp, g_WKlo);
    cudaGetSymbolAddress((void**)&WQhp, g_WQhi);
    cudaGetSymbolAddress((void**)&WQlp, g_WQlo);

    // 1) fused gate + conversions
    pre_kernel<<<PRE_BLKS, 256>>>(g_feat, W_g, b_g, gwp,
                                  a_feat, W_K, W_Q,
                                  Ahp, Alp, WKhp, WKlp, WQhp, WQlp);

    // 2) K & Q GEMMs (128x128 CTA, 64x64 warp tile, KC=32, 3-stage, 2 CTA/SM)
    cudaFuncSetAttribute(gemm_mma, cudaFuncAttributeMaxDynamicSharedMemorySize,
                         GEMM_SMEM);
    dim3 ggrid(KQ_COLS / 128, P_ / 128, 2);   // (8, 50, 2)
    gemm_mma<<<ggrid, 128, GEMM_SMEM>>>(Ahp, Alp, WKhp, WKlp, WQhp, WQlp,
                                        b_K, b_Q, Kp, Qp);

    // 3) logits (e overwrites gw in place)
    int lsmem = 2 * 112 * KQPAD * (int)sizeof(float);
    cudaFuncSetAttribute(attn_logits_kernel,
                         cudaFuncAttributeMaxDynamicSharedMemorySize, lsmem);
    dim3 agrid(NR_, B_);
    attn_logits_kernel<<<agrid, 256, lsmem>>>(Kp, Qp, gwp);

    // 4) AV + normalize + affine
    cudaFuncSetAttribute(attn_av_kernel,
                         cudaFuncAttributeMaxDynamicSharedMemorySize, AV_SMEM);
    attn_av_kernel<<<agrid, 256, AV_SMEM>>>(gwp, a_feat, w_s, b_s, out);
}